// round 1
// baseline (speedup 1.0000x reference)
#include <cuda_runtime.h>
#include <cuda_bf16.h>
#include <cstdint>

#define NN 100000
#define NE 1600000
#define DD 128

typedef unsigned long long ull;

// Scratch (allocation-free rule: static __device__ arrays)
__device__ float g_h[(size_t)NN * DD];   // 51.2 MB: h = x @ W.T + b
__device__ int   g_deg[NN];

// ---------------- f32x2 packed-FMA helpers (sm_100+ PTX) ----------------
__device__ __forceinline__ ull ff2_pack(float lo, float hi) {
    ull r;
    asm("mov.b64 %0, {%1, %2};" : "=l"(r)
        : "r"(__float_as_uint(lo)), "r"(__float_as_uint(hi)));
    return r;
}
__device__ __forceinline__ void ff2_unpack(ull v, float& lo, float& hi) {
    unsigned int a, b;
    asm("mov.b64 {%0, %1}, %2;" : "=r"(a), "=r"(b) : "l"(v));
    lo = __uint_as_float(a);
    hi = __uint_as_float(b);
}
__device__ __forceinline__ ull ff2_fma(ull a, ull b, ull c) {
    ull d;
    asm("fma.rn.f32x2 %0, %1, %2, %3;" : "=l"(d) : "l"(a), "l"(b), "l"(c));
    return d;
}

// ---------------- GEMM: h[m][c] = sum_k x[m][k] * W[c][k] + b[c] ----------------
// Block: 256 threads, tile 64 rows x 128 cols, K chunked by 32.
// Thread (tx=tid&15, ty=tid>>4) computes rows ty*4..ty*4+3, cols {tx*4..+3, 64+tx*4..+3}.
__global__ void __launch_bounds__(256) gemm_kernel(const float* __restrict__ X,
                                                   const float* __restrict__ W,
                                                   const float* __restrict__ B) {
    __shared__ float xs[32][68];   // xs[kk][m], padded for 16B-aligned float4 reads
    __shared__ float ws[32][132];  // ws[kk][c]

    const int tid = threadIdx.x;
    const int tx = tid & 15;
    const int ty = tid >> 4;
    const int r0 = blockIdx.x * 64;

    ull acc[4][4];
#pragma unroll
    for (int i = 0; i < 4; i++)
#pragma unroll
        for (int j = 0; j < 4; j++) acc[i][j] = 0ull;  // (0.f, 0.f)

    for (int k0 = 0; k0 < DD; k0 += 32) {
        // load x tile (64 rows x 32 k), transpose into xs[kk][row]
#pragma unroll
        for (int i = 0; i < 2; i++) {
            int idx = tid + i * 256;           // 512 float4 total
            int row = idx >> 3;                // 8 float4 per row
            int kq  = idx & 7;
            float4 v = make_float4(0.f, 0.f, 0.f, 0.f);
            int gr = r0 + row;
            if (gr < NN)
                v = *(const float4*)(X + (size_t)gr * DD + k0 + kq * 4);
            xs[kq * 4 + 0][row] = v.x;
            xs[kq * 4 + 1][row] = v.y;
            xs[kq * 4 + 2][row] = v.z;
            xs[kq * 4 + 3][row] = v.w;
        }
        // load W tile (128 cols x 32 k), transpose into ws[kk][col]
#pragma unroll
        for (int i = 0; i < 4; i++) {
            int idx = tid + i * 256;           // 1024 float4 total
            int col = idx >> 3;
            int kq  = idx & 7;
            float4 v = *(const float4*)(W + (size_t)col * DD + k0 + kq * 4);
            ws[kq * 4 + 0][col] = v.x;
            ws[kq * 4 + 1][col] = v.y;
            ws[kq * 4 + 2][col] = v.z;
            ws[kq * 4 + 3][col] = v.w;
        }
        __syncthreads();

#pragma unroll 8
        for (int kk = 0; kk < 32; kk++) {
            float4 av  = *(const float4*)&xs[kk][ty * 4];
            float4 bv0 = *(const float4*)&ws[kk][tx * 4];
            float4 bv1 = *(const float4*)&ws[kk][64 + tx * 4];
            ull a2[4];
            a2[0] = ff2_pack(av.x, av.x);
            a2[1] = ff2_pack(av.y, av.y);
            a2[2] = ff2_pack(av.z, av.z);
            a2[3] = ff2_pack(av.w, av.w);
            ull b2[4];
            b2[0] = ff2_pack(bv0.x, bv0.y);
            b2[1] = ff2_pack(bv0.z, bv0.w);
            b2[2] = ff2_pack(bv1.x, bv1.y);
            b2[3] = ff2_pack(bv1.z, bv1.w);
#pragma unroll
            for (int i = 0; i < 4; i++)
#pragma unroll
                for (int j = 0; j < 4; j++)
                    acc[i][j] = ff2_fma(a2[i], b2[j], acc[i][j]);
        }
        __syncthreads();
    }

    // epilogue: +bias, store to g_h
    float4 bb0 = *(const float4*)(B + tx * 4);
    float4 bb1 = *(const float4*)(B + 64 + tx * 4);
#pragma unroll
    for (int i = 0; i < 4; i++) {
        int gr = r0 + ty * 4 + i;
        if (gr >= NN) continue;
        float4 o0, o1;
        ff2_unpack(acc[i][0], o0.x, o0.y);
        ff2_unpack(acc[i][1], o0.z, o0.w);
        ff2_unpack(acc[i][2], o1.x, o1.y);
        ff2_unpack(acc[i][3], o1.z, o1.w);
        o0.x += bb0.x; o0.y += bb0.y; o0.z += bb0.z; o0.w += bb0.w;
        o1.x += bb1.x; o1.y += bb1.y; o1.z += bb1.z; o1.w += bb1.w;
        *(float4*)(g_h + (size_t)gr * DD + tx * 4)      = o0;
        *(float4*)(g_h + (size_t)gr * DD + 64 + tx * 4) = o1;
    }
}

// ---------------- init: zero accumulator (d_out) and deg=1 (self-loop) ----------------
__global__ void init_kernel(float4* __restrict__ out4) {
    int idx = blockIdx.x * blockDim.x + threadIdx.x;
    if (idx < NN * (DD / 4)) out4[idx] = make_float4(0.f, 0.f, 0.f, 0.f);
    if (idx < NN) g_deg[idx] = 1;
}

// ---------------- degree count ----------------
__global__ void deg_kernel(const int* __restrict__ er) {
    int idx = blockIdx.x * blockDim.x + threadIdx.x;
    if (idx < NE) atomicAdd(&g_deg[er[idx]], 1);
}

// ---------------- scatter: out[row] += h[col] (one warp per edge) ----------------
__global__ void __launch_bounds__(256) scatter_kernel(const int* __restrict__ er,
                                                      const int* __restrict__ ec,
                                                      float* __restrict__ out) {
    int gtid = blockIdx.x * blockDim.x + threadIdx.x;
    int e = gtid >> 5;
    int lane = gtid & 31;
    if (e >= NE) return;
    int r = er[e];
    int c = ec[e];
    float4 hv = *(const float4*)(g_h + (size_t)c * DD + lane * 4);
    atomicAdd((float4*)(out + (size_t)r * DD + lane * 4), hv);
}

// ---------------- finalize: out = relu((out + h) / deg) in-place ----------------
__global__ void finalize_kernel(float4* __restrict__ out4) {
    int idx = blockIdx.x * blockDim.x + threadIdx.x;
    if (idx >= NN * (DD / 4)) return;
    int node = idx >> 5;  // 32 float4 per node
    float inv = 1.0f / (float)g_deg[node];
    float4 o = out4[idx];
    const float4 h = *(const float4*)(g_h + (size_t)idx * 4);
    o.x = fmaxf((o.x + h.x) * inv, 0.f);
    o.y = fmaxf((o.y + h.y) * inv, 0.f);
    o.z = fmaxf((o.z + h.z) * inv, 0.f);
    o.w = fmaxf((o.w + h.w) * inv, 0.f);
    out4[idx] = o;
}

extern "C" void kernel_launch(void* const* d_in, const int* in_sizes, int n_in,
                              void* d_out, int out_size) {
    const float* x  = (const float*)d_in[0];
    const float* W  = (const float*)d_in[1];
    const float* b  = (const float*)d_in[2];
    const int* er   = (const int*)d_in[3];
    const int* ec   = (const int*)d_in[4];
    float* out      = (float*)d_out;

    // 1) zero accumulator (d_out) + deg=1
    init_kernel<<<(NN * (DD / 4) + 255) / 256, 256>>>((float4*)out);
    // 2) GEMM h = x @ W.T + b
    gemm_kernel<<<(NN + 63) / 64, 256>>>(x, W, b);
    // 3) degree count
    deg_kernel<<<(NE + 255) / 256, 256>>>(er);
    // 4) edge scatter (warp per edge, float4 atomics)
    scatter_kernel<<<(NE * 32) / 256, 256>>>(er, ec, out);
    // 5) finalize: add self-loop h, normalize by deg, relu
    finalize_kernel<<<(NN * (DD / 4) + 255) / 256, 256>>>((float4*)out);
}

// round 2
// speedup vs baseline: 1.7464x; 1.7464x over previous
#include <cuda_runtime.h>
#include <cuda_bf16.h>
#include <cstdint>

#define NN 100000
#define NE 1600000
#define DD 128
#define NB ((NN + 1023) / 1024)   // 98 scan blocks

typedef unsigned long long ull;

// Scratch (allocation-free rule: static __device__ arrays)
__device__ float g_h[(size_t)NN * DD];   // 51.2 MB: h = x @ W.T + b
__device__ int   g_deg[NN];
__device__ int   g_off[NN + 1];
__device__ int   g_cur[NN];
__device__ int   g_col[NE];
__device__ int   g_bsum[128];
__device__ int   g_boff[128];

// ---------------- f32x2 packed-FMA helpers (sm_100+ PTX) ----------------
__device__ __forceinline__ ull ff2_pack(float lo, float hi) {
    ull r;
    asm("mov.b64 %0, {%1, %2};" : "=l"(r)
        : "r"(__float_as_uint(lo)), "r"(__float_as_uint(hi)));
    return r;
}
__device__ __forceinline__ void ff2_unpack(ull v, float& lo, float& hi) {
    unsigned int a, b;
    asm("mov.b64 {%0, %1}, %2;" : "=r"(a), "=r"(b) : "l"(v));
    lo = __uint_as_float(a);
    hi = __uint_as_float(b);
}
__device__ __forceinline__ ull ff2_fma(ull a, ull b, ull c) {
    ull d;
    asm("fma.rn.f32x2 %0, %1, %2, %3;" : "=l"(d) : "l"(a), "l"(b), "l"(c));
    return d;
}

// ---------------- GEMM: h[m][c] = sum_k x[m][k] * W[c][k] + b[c] ----------------
__global__ void __launch_bounds__(256) gemm_kernel(const float* __restrict__ X,
                                                   const float* __restrict__ W,
                                                   const float* __restrict__ B) {
    __shared__ float xs[32][68];   // xs[kk][m]
    __shared__ float ws[32][132];  // ws[kk][c]

    const int tid = threadIdx.x;
    const int tx = tid & 15;
    const int ty = tid >> 4;
    const int r0 = blockIdx.x * 64;

    ull acc[4][4];
#pragma unroll
    for (int i = 0; i < 4; i++)
#pragma unroll
        for (int j = 0; j < 4; j++) acc[i][j] = 0ull;

    for (int k0 = 0; k0 < DD; k0 += 32) {
#pragma unroll
        for (int i = 0; i < 2; i++) {
            int idx = tid + i * 256;
            int row = idx >> 3;
            int kq  = idx & 7;
            float4 v = make_float4(0.f, 0.f, 0.f, 0.f);
            int gr = r0 + row;
            if (gr < NN)
                v = *(const float4*)(X + (size_t)gr * DD + k0 + kq * 4);
            xs[kq * 4 + 0][row] = v.x;
            xs[kq * 4 + 1][row] = v.y;
            xs[kq * 4 + 2][row] = v.z;
            xs[kq * 4 + 3][row] = v.w;
        }
#pragma unroll
        for (int i = 0; i < 4; i++) {
            int idx = tid + i * 256;
            int col = idx >> 3;
            int kq  = idx & 7;
            float4 v = *(const float4*)(W + (size_t)col * DD + k0 + kq * 4);
            ws[kq * 4 + 0][col] = v.x;
            ws[kq * 4 + 1][col] = v.y;
            ws[kq * 4 + 2][col] = v.z;
            ws[kq * 4 + 3][col] = v.w;
        }
        __syncthreads();

#pragma unroll 8
        for (int kk = 0; kk < 32; kk++) {
            float4 av  = *(const float4*)&xs[kk][ty * 4];
            float4 bv0 = *(const float4*)&ws[kk][tx * 4];
            float4 bv1 = *(const float4*)&ws[kk][64 + tx * 4];
            ull a2[4];
            a2[0] = ff2_pack(av.x, av.x);
            a2[1] = ff2_pack(av.y, av.y);
            a2[2] = ff2_pack(av.z, av.z);
            a2[3] = ff2_pack(av.w, av.w);
            ull b2[4];
            b2[0] = ff2_pack(bv0.x, bv0.y);
            b2[1] = ff2_pack(bv0.z, bv0.w);
            b2[2] = ff2_pack(bv1.x, bv1.y);
            b2[3] = ff2_pack(bv1.z, bv1.w);
#pragma unroll
            for (int i = 0; i < 4; i++)
#pragma unroll
                for (int j = 0; j < 4; j++)
                    acc[i][j] = ff2_fma(a2[i], b2[j], acc[i][j]);
        }
        __syncthreads();
    }

    float4 bb0 = *(const float4*)(B + tx * 4);
    float4 bb1 = *(const float4*)(B + 64 + tx * 4);
#pragma unroll
    for (int i = 0; i < 4; i++) {
        int gr = r0 + ty * 4 + i;
        if (gr >= NN) continue;
        float4 o0, o1;
        ff2_unpack(acc[i][0], o0.x, o0.y);
        ff2_unpack(acc[i][1], o0.z, o0.w);
        ff2_unpack(acc[i][2], o1.x, o1.y);
        ff2_unpack(acc[i][3], o1.z, o1.w);
        o0.x += bb0.x; o0.y += bb0.y; o0.z += bb0.z; o0.w += bb0.w;
        o1.x += bb1.x; o1.y += bb1.y; o1.z += bb1.z; o1.w += bb1.w;
        *(float4*)(g_h + (size_t)gr * DD + tx * 4)      = o0;
        *(float4*)(g_h + (size_t)gr * DD + 64 + tx * 4) = o1;
    }
}

// ---------------- CSR build ----------------
__global__ void zero_deg_kernel() {
    int i = blockIdx.x * blockDim.x + threadIdx.x;
    if (i < NN) g_deg[i] = 0;
}

__global__ void hist_kernel(const int* __restrict__ er) {
    int i = blockIdx.x * blockDim.x + threadIdx.x;
    if (i < NE) atomicAdd(&g_deg[er[i]], 1);
}

// scan pass A: per-block (1024 elems) totals
__global__ void __launch_bounds__(256) scanA_kernel() {
    __shared__ int sh[256];
    int base = blockIdx.x * 1024 + threadIdx.x * 4;
    int s = 0;
#pragma unroll
    for (int k = 0; k < 4; k++) {
        int i = base + k;
        if (i < NN) s += g_deg[i];
    }
    sh[threadIdx.x] = s;
    __syncthreads();
    for (int off = 128; off > 0; off >>= 1) {
        if (threadIdx.x < off) sh[threadIdx.x] += sh[threadIdx.x + off];
        __syncthreads();
    }
    if (threadIdx.x == 0) g_bsum[blockIdx.x] = sh[0];
}

// scan pass B: exclusive scan of the 98 block sums (single block)
__global__ void scanB_kernel() {
    __shared__ int sh[128];
    int v = (threadIdx.x < NB) ? g_bsum[threadIdx.x] : 0;
    sh[threadIdx.x] = v;
    __syncthreads();
    for (int off = 1; off < 128; off <<= 1) {
        int t = (threadIdx.x >= off) ? sh[threadIdx.x - off] : 0;
        __syncthreads();
        sh[threadIdx.x] += t;
        __syncthreads();
    }
    if (threadIdx.x < NB) g_boff[threadIdx.x] = sh[threadIdx.x] - v;
}

// scan pass C: element-wise exclusive prefix -> offsets + cursor
__global__ void __launch_bounds__(256) scanC_kernel() {
    __shared__ int sh[256];
    int tid = threadIdx.x;
    int base = blockIdx.x * 1024 + tid * 4;
    int vals[4];
    int s = 0;
#pragma unroll
    for (int k = 0; k < 4; k++) {
        int i = base + k;
        vals[k] = (i < NN) ? g_deg[i] : 0;
        s += vals[k];
    }
    sh[tid] = s;
    __syncthreads();
    for (int off = 1; off < 256; off <<= 1) {
        int t = (tid >= off) ? sh[tid - off] : 0;
        __syncthreads();
        sh[tid] += t;
        __syncthreads();
    }
    int excl = sh[tid] - s + g_boff[blockIdx.x];
#pragma unroll
    for (int k = 0; k < 4; k++) {
        int i = base + k;
        if (i < NN) { g_off[i] = excl; g_cur[i] = excl; }
        excl += vals[k];
    }
    if (blockIdx.x == NB - 1 && tid == 255) g_off[NN] = excl;
}

// permute edges into CSR order
__global__ void permute_kernel(const int* __restrict__ er, const int* __restrict__ ec) {
    int e = blockIdx.x * blockDim.x + threadIdx.x;
    if (e < NE) {
        int pos = atomicAdd(&g_cur[er[e]], 1);
        g_col[pos] = ec[e];
    }
}

// ---------------- gather: out[i] = relu( (h[i] + sum_{j in N(i)} h[j]) / (deg+1) ) ----------------
__global__ void __launch_bounds__(256) gather_kernel(float* __restrict__ out) {
    int warp = (blockIdx.x * 256 + threadIdx.x) >> 5;
    int lane = threadIdx.x & 31;
    if (warp >= NN) return;
    int beg = g_off[warp];
    int end = g_off[warp + 1];

    // self-loop
    float4 acc = *(const float4*)(g_h + (size_t)warp * DD + lane * 4);

    int e = beg;
    for (; e + 4 <= end; e += 4) {
        int c0 = g_col[e + 0];
        int c1 = g_col[e + 1];
        int c2 = g_col[e + 2];
        int c3 = g_col[e + 3];
        float4 v0 = *(const float4*)(g_h + (size_t)c0 * DD + lane * 4);
        float4 v1 = *(const float4*)(g_h + (size_t)c1 * DD + lane * 4);
        float4 v2 = *(const float4*)(g_h + (size_t)c2 * DD + lane * 4);
        float4 v3 = *(const float4*)(g_h + (size_t)c3 * DD + lane * 4);
        acc.x += v0.x + v1.x + v2.x + v3.x;
        acc.y += v0.y + v1.y + v2.y + v3.y;
        acc.z += v0.z + v1.z + v2.z + v3.z;
        acc.w += v0.w + v1.w + v2.w + v3.w;
    }
    for (; e < end; e++) {
        int c = g_col[e];
        float4 v = *(const float4*)(g_h + (size_t)c * DD + lane * 4);
        acc.x += v.x; acc.y += v.y; acc.z += v.z; acc.w += v.w;
    }

    float inv = 1.0f / (float)(end - beg + 1);
    acc.x = fmaxf(acc.x * inv, 0.f);
    acc.y = fmaxf(acc.y * inv, 0.f);
    acc.z = fmaxf(acc.z * inv, 0.f);
    acc.w = fmaxf(acc.w * inv, 0.f);
    *(float4*)(out + (size_t)warp * DD + lane * 4) = acc;
}

extern "C" void kernel_launch(void* const* d_in, const int* in_sizes, int n_in,
                              void* d_out, int out_size) {
    const float* x  = (const float*)d_in[0];
    const float* W  = (const float*)d_in[1];
    const float* b  = (const float*)d_in[2];
    const int* er   = (const int*)d_in[3];
    const int* ec   = (const int*)d_in[4];
    float* out      = (float*)d_out;

    // CSR build
    zero_deg_kernel<<<(NN + 255) / 256, 256>>>();
    hist_kernel<<<(NE + 255) / 256, 256>>>(er);
    scanA_kernel<<<NB, 256>>>();
    scanB_kernel<<<1, 128>>>();
    scanC_kernel<<<NB, 256>>>();
    permute_kernel<<<(NE + 255) / 256, 256>>>(er, ec);

    // GEMM h = x @ W.T + b
    gemm_kernel<<<(NN + 63) / 64, 256>>>(x, W, b);

    // gather + normalize + relu (writes d_out directly)
    gather_kernel<<<(NN * 32 + 255) / 256, 256>>>(out);
}

// round 4
// speedup vs baseline: 2.3983x; 1.3733x over previous
#include <cuda_runtime.h>
#include <cuda_bf16.h>
#include <cstdint>

#define NN 100000
#define NE 1600000
#define DD 128
#define NB ((NN + 1023) / 1024)     // 98 scan blocks
#define NTILE ((NN + 127) / 128)    // 782 GEMM tiles
#define ROWPAD 136                  // bf16 elems per SMEM row (272B, conflict-free)

typedef unsigned long long ull;

// ---------------- scratch (__device__ globals; no allocation allowed) ----------------
__device__ float g_h[(size_t)NN * DD];   // 51.2 MB: h = x @ W.T + b
__device__ int   g_deg[NN];
__device__ int   g_off[NN + 1];
__device__ int   g_cur[NN];
__device__ int   g_col[NE];
__device__ int   g_bsum[128];
__device__ int   g_boff[128];
// Pre-fragmented W for mma.sync: [nt(16)][ks(8)][r(2)][lane(32)] uint32 (b16 pairs)
__device__ uint32_t g_Bfrag_hi[8192];
__device__ uint32_t g_Bfrag_lo[8192];

__device__ __forceinline__ uint32_t smem_u32(const void* p) {
    uint32_t a;
    asm("{ .reg .u64 t; cvta.to.shared.u64 t, %1; cvt.u32.u64 %0, t; }" : "=r"(a) : "l"(p));
    return a;
}
__device__ __forceinline__ unsigned short bfu(float v) {
    return __bfloat16_as_ushort(__float2bfloat16(v));
}

// ---------------- W pre-fragment: fp32 -> (hi, lo) bf16 mma fragments ----------------
__global__ void wconv_kernel(const float* __restrict__ W) {
    int idx = blockIdx.x * blockDim.x + threadIdx.x;
    if (idx >= 8192) return;
    int lane = idx & 31;
    int r    = (idx >> 5) & 1;
    int ks   = (idx >> 6) & 7;
    int nt   = idx >> 9;
    int n = nt * 8 + (lane >> 2);
    int k = ks * 16 + r * 8 + (lane & 3) * 2;
    float v0 = W[n * DD + k];
    float v1 = W[n * DD + k + 1];
    __nv_bfloat16 h0 = __float2bfloat16(v0), h1 = __float2bfloat16(v1);
    uint32_t hi = ((uint32_t)__bfloat16_as_ushort(h1) << 16) | __bfloat16_as_ushort(h0);
    uint32_t lo = ((uint32_t)bfu(v1 - __bfloat162float(h1)) << 16) | bfu(v0 - __bfloat162float(h0));
    g_Bfrag_hi[idx] = hi;
    g_Bfrag_lo[idx] = lo;
}

// ---------------- GEMM: h = x @ W.T + b via HMMA (3-term bf16 split) ----------------
__device__ __forceinline__ void mma_bf16(float* c, const uint32_t* a, uint32_t b0, uint32_t b1) {
    asm volatile(
        "mma.sync.aligned.m16n8k16.row.col.f32.bf16.bf16.f32 "
        "{%0,%1,%2,%3}, {%4,%5,%6,%7}, {%8,%9}, {%0,%1,%2,%3};"
        : "+f"(c[0]), "+f"(c[1]), "+f"(c[2]), "+f"(c[3])
        : "r"(a[0]), "r"(a[1]), "r"(a[2]), "r"(a[3]), "r"(b0), "r"(b1));
}
__device__ __forceinline__ void ldm_x4(uint32_t* a, uint32_t addr) {
    asm volatile("ldmatrix.sync.aligned.m8n8.x4.shared.b16 {%0,%1,%2,%3}, [%4];"
                 : "=r"(a[0]), "=r"(a[1]), "=r"(a[2]), "=r"(a[3]) : "r"(addr));
}

#define GSMEM (2 * 128 * ROWPAD * 2)   // A_hi + A_lo, 69632 B

__global__ void __launch_bounds__(256) gemm_mma_kernel(const float* __restrict__ X,
                                                       const float* __restrict__ Bias) {
    extern __shared__ char smem[];
    __nv_bfloat16* Ah = (__nv_bfloat16*)smem;
    __nv_bfloat16* Al = (__nv_bfloat16*)(smem + 128 * ROWPAD * 2);

    const int tid = threadIdx.x;
    const int w = tid >> 5;
    const int lane = tid & 31;
    const int r0 = blockIdx.x * 128;

    // ---- load X tile, split-convert to hi/lo bf16 in SMEM ----
#pragma unroll
    for (int it = 0; it < 16; it++) {
        int idx = tid + it * 256;          // 4096 float4
        int row = idx >> 5;
        int kq  = idx & 31;
        float4 v = make_float4(0.f, 0.f, 0.f, 0.f);
        if (r0 + row < NN) v = *(const float4*)(X + (size_t)(r0 + row) * DD + kq * 4);
        __nv_bfloat16 hx = __float2bfloat16(v.x), hy = __float2bfloat16(v.y);
        __nv_bfloat16 hz = __float2bfloat16(v.z), hw = __float2bfloat16(v.w);
        uint32_t hi01 = ((uint32_t)__bfloat16_as_ushort(hy) << 16) | __bfloat16_as_ushort(hx);
        uint32_t hi23 = ((uint32_t)__bfloat16_as_ushort(hw) << 16) | __bfloat16_as_ushort(hz);
        uint32_t lo01 = ((uint32_t)bfu(v.y - __bfloat162float(hy)) << 16) | bfu(v.x - __bfloat162float(hx));
        uint32_t lo23 = ((uint32_t)bfu(v.w - __bfloat162float(hw)) << 16) | bfu(v.z - __bfloat162float(hz));
        *(ull*)(Ah + row * ROWPAD + kq * 4) = ((ull)hi23 << 32) | hi01;
        *(ull*)(Al + row * ROWPAD + kq * 4) = ((ull)lo23 << 32) | lo01;
    }

    // ---- load resident B fragments (warp w owns cols 16w..16w+15 = n-tiles 2w, 2w+1) ----
    uint32_t bh[2][8][2], bl[2][8][2];
#pragma unroll
    for (int t = 0; t < 2; t++)
#pragma unroll
        for (int ks = 0; ks < 8; ks++)
#pragma unroll
            for (int r = 0; r < 2; r++) {
                int gi = (((2 * w + t) * 8 + ks) * 2 + r) * 32 + lane;
                bh[t][ks][r] = g_Bfrag_hi[gi];
                bl[t][ks][r] = g_Bfrag_lo[gi];
            }

    const int t2 = lane & 3;
    const int g  = lane >> 2;
    float2 bias0 = *(const float2*)(Bias + w * 16 + t2 * 2);
    float2 bias1 = *(const float2*)(Bias + w * 16 + 8 + t2 * 2);

    __syncthreads();

    const uint32_t ah_base = smem_u32(Ah);
    const uint32_t al_base = smem_u32(Al);
    // ldmatrix per-lane row address offset (bytes)
    const uint32_t rowoff =
        ((((lane >> 3) & 1) * 8 + (lane & 7)) * ROWPAD + (lane >> 4) * 8) * 2;

#pragma unroll
    for (int mt = 0; mt < 8; mt++) {
        float acc0[4] = {0.f, 0.f, 0.f, 0.f};
        float acc1[4] = {0.f, 0.f, 0.f, 0.f};
#pragma unroll
        for (int ks = 0; ks < 8; ks++) {
            uint32_t off = (uint32_t)(mt * 16 * ROWPAD * 2 + ks * 32) + rowoff;
            uint32_t ah[4], al[4];
            ldm_x4(ah, ah_base + off);
            ldm_x4(al, al_base + off);
            mma_bf16(acc0, ah, bh[0][ks][0], bh[0][ks][1]);
            mma_bf16(acc1, ah, bh[1][ks][0], bh[1][ks][1]);
            mma_bf16(acc0, ah, bl[0][ks][0], bl[0][ks][1]);
            mma_bf16(acc1, ah, bl[1][ks][0], bl[1][ks][1]);
            mma_bf16(acc0, al, bh[0][ks][0], bh[0][ks][1]);
            mma_bf16(acc1, al, bh[1][ks][0], bh[1][ks][1]);
        }
        int row = r0 + mt * 16 + g;
        int col0 = w * 16 + t2 * 2;
        if (row < NN) {
            float* p = g_h + (size_t)row * DD;
            *(float2*)(p + col0)     = make_float2(acc0[0] + bias0.x, acc0[1] + bias0.y);
            *(float2*)(p + col0 + 8) = make_float2(acc1[0] + bias1.x, acc1[1] + bias1.y);
        }
        if (row + 8 < NN) {
            float* p = g_h + (size_t)(row + 8) * DD;
            *(float2*)(p + col0)     = make_float2(acc0[2] + bias0.x, acc0[3] + bias0.y);
            *(float2*)(p + col0 + 8) = make_float2(acc1[2] + bias1.x, acc1[3] + bias1.y);
        }
    }
}

// ---------------- CSR build ----------------
__global__ void zero_deg_kernel() {
    int i = blockIdx.x * blockDim.x + threadIdx.x;
    if (i < NN) g_deg[i] = 0;
}

__global__ void hist_kernel(const int* __restrict__ er) {
    int i = blockIdx.x * blockDim.x + threadIdx.x;
    if (i < NE) atomicAdd(&g_deg[er[i]], 1);
}

__global__ void __launch_bounds__(256) scanA_kernel() {
    __shared__ int sh[256];
    int base = blockIdx.x * 1024 + threadIdx.x * 4;
    int s = 0;
#pragma unroll
    for (int k = 0; k < 4; k++) {
        int i = base + k;
        if (i < NN) s += g_deg[i];
    }
    sh[threadIdx.x] = s;
    __syncthreads();
    for (int off = 128; off > 0; off >>= 1) {
        if (threadIdx.x < off) sh[threadIdx.x] += sh[threadIdx.x + off];
        __syncthreads();
    }
    if (threadIdx.x == 0) g_bsum[blockIdx.x] = sh[0];
}

__global__ void scanB_kernel() {
    __shared__ int sh[128];
    int v = (threadIdx.x < NB) ? g_bsum[threadIdx.x] : 0;
    sh[threadIdx.x] = v;
    __syncthreads();
    for (int off = 1; off < 128; off <<= 1) {
        int t = (threadIdx.x >= off) ? sh[threadIdx.x - off] : 0;
        __syncthreads();
        sh[threadIdx.x] += t;
        __syncthreads();
    }
    if (threadIdx.x < NB) g_boff[threadIdx.x] = sh[threadIdx.x] - v;
}

__global__ void __launch_bounds__(256) scanC_kernel() {
    __shared__ int sh[256];
    int tid = threadIdx.x;
    int base = blockIdx.x * 1024 + tid * 4;
    int vals[4];
    int s = 0;
#pragma unroll
    for (int k = 0; k < 4; k++) {
        int i = base + k;
        vals[k] = (i < NN) ? g_deg[i] : 0;
        s += vals[k];
    }
    sh[tid] = s;
    __syncthreads();
    for (int off = 1; off < 256; off <<= 1) {
        int t = (tid >= off) ? sh[tid - off] : 0;
        __syncthreads();
        sh[tid] += t;
        __syncthreads();
    }
    int excl = sh[tid] - s + g_boff[blockIdx.x];
#pragma unroll
    for (int k = 0; k < 4; k++) {
        int i = base + k;
        if (i < NN) { g_off[i] = excl; g_cur[i] = excl; }
        excl += vals[k];
    }
    if (blockIdx.x == NB - 1 && tid == 255) g_off[NN] = excl;
}

__global__ void permute_kernel(const int* __restrict__ er, const int* __restrict__ ec) {
    int e = blockIdx.x * blockDim.x + threadIdx.x;
    if (e < NE) {
        int pos = atomicAdd(&g_cur[er[e]], 1);
        g_col[pos] = ec[e];
    }
}

// ---------------- gather: out[i] = relu( (h[i] + sum_j h[col_j]) / (deg+1) ) ----------------
__global__ void __launch_bounds__(256) gather_kernel(float* __restrict__ out) {
    int warp = (blockIdx.x * 256 + threadIdx.x) >> 5;
    int lane = threadIdx.x & 31;
    if (warp >= NN) return;
    int beg = g_off[warp];
    int end = g_off[warp + 1];

    float4 acc = *(const float4*)(g_h + (size_t)warp * DD + lane * 4);

    int e = beg;
    for (; e + 4 <= end; e += 4) {
        int c0 = g_col[e + 0];
        int c1 = g_col[e + 1];
        int c2 = g_col[e + 2];
        int c3 = g_col[e + 3];
        float4 v0 = *(const float4*)(g_h + (size_t)c0 * DD + lane * 4);
        float4 v1 = *(const float4*)(g_h + (size_t)c1 * DD + lane * 4);
        float4 v2 = *(const float4*)(g_h + (size_t)c2 * DD + lane * 4);
        float4 v3 = *(const float4*)(g_h + (size_t)c3 * DD + lane * 4);
        acc.x += v0.x + v1.x + v2.x + v3.x;
        acc.y += v0.y + v1.y + v2.y + v3.y;
        acc.z += v0.z + v1.z + v2.z + v3.z;
        acc.w += v0.w + v1.w + v2.w + v3.w;
    }
    for (; e < end; e++) {
        int c = g_col[e];
        float4 v = *(const float4*)(g_h + (size_t)c * DD + lane * 4);
        acc.x += v.x; acc.y += v.y; acc.z += v.z; acc.w += v.w;
    }

    float inv = 1.0f / (float)(end - beg + 1);
    acc.x = fmaxf(acc.x * inv, 0.f);
    acc.y = fmaxf(acc.y * inv, 0.f);
    acc.z = fmaxf(acc.z * inv, 0.f);
    acc.w = fmaxf(acc.w * inv, 0.f);
    *(float4*)(out + (size_t)warp * DD + lane * 4) = acc;
}

extern "C" void kernel_launch(void* const* d_in, const int* in_sizes, int n_in,
                              void* d_out, int out_size) {
    const float* x  = (const float*)d_in[0];
    const float* W  = (const float*)d_in[1];
    const float* b  = (const float*)d_in[2];
    const int* er   = (const int*)d_in[3];
    const int* ec   = (const int*)d_in[4];
    float* out      = (float*)d_out;

    // W -> bf16 hi/lo mma fragment images
    wconv_kernel<<<16, 512>>>(W);

    // CSR build
    zero_deg_kernel<<<(NN + 255) / 256, 256>>>();
    hist_kernel<<<(NE + 255) / 256, 256>>>(er);
    scanA_kernel<<<NB, 256>>>();
    scanB_kernel<<<1, 128>>>();
    scanC_kernel<<<NB, 256>>>();
    permute_kernel<<<(NE + 255) / 256, 256>>>(er, ec);

    // GEMM h = x @ W.T + b (HMMA, 3-term bf16 split)
    cudaFuncSetAttribute(gemm_mma_kernel, cudaFuncAttributeMaxDynamicSharedMemorySize, GSMEM);
    gemm_mma_kernel<<<NTILE, 256, GSMEM>>>(x, b);

    // gather + normalize + relu
    gather_kernel<<<(NN * 32 + 255) / 256, 256>>>(out);
}

// round 5
// speedup vs baseline: 2.5364x; 1.0576x over previous
#include <cuda_runtime.h>
#include <cuda_bf16.h>
#include <cuda_fp16.h>
#include <cstdint>

#define NN 100000
#define NE 1600000
#define DD 128
#define NB ((NN + 1023) / 1024)     // 98 scan blocks
#define NTILE ((NN + 127) / 128)    // 782 GEMM tiles
#define ROWPAD 136                  // bf16 elems per SMEM row (272B, conflict-free)

typedef unsigned long long ull;

// ---------------- scratch (__device__ globals; no allocation allowed) ----------------
__device__ float  g_h[(size_t)NN * DD];    // 51.2 MB fp32 h = x @ W.T + b
__device__ __half g_hf[(size_t)NN * DD];   // 25.6 MB fp16 mirror for gather
__device__ int    g_deg[NN];
__device__ int    g_off[NN + 1];
__device__ int    g_cur[NN];
__device__ int    g_col[NE];
__device__ ull    g_lb[NB];                // lookback state: (state<<32)|value
// Pre-fragmented W for mma.sync: [nt(16)][ks(8)][r(2)][lane(32)] uint32 (b16 pairs)
__device__ uint32_t g_Bfrag_hi[8192];
__device__ uint32_t g_Bfrag_lo[8192];

__device__ __forceinline__ uint32_t smem_u32(const void* p) {
    uint32_t a;
    asm("{ .reg .u64 t; cvta.to.shared.u64 t, %1; cvt.u32.u64 %0, t; }" : "=r"(a) : "l"(p));
    return a;
}
__device__ __forceinline__ unsigned short bfu(float v) {
    return __bfloat16_as_ushort(__float2bfloat16(v));
}

// ---------------- prep: W fragments + zero deg + zero lookback ----------------
__global__ void prep_kernel(const float* __restrict__ W) {
    int idx = blockIdx.x * blockDim.x + threadIdx.x;
    if (idx < 8192) {
        int lane = idx & 31;
        int r    = (idx >> 5) & 1;
        int ks   = (idx >> 6) & 7;
        int nt   = idx >> 9;
        int n = nt * 8 + (lane >> 2);
        int k = ks * 16 + r * 8 + (lane & 3) * 2;
        float v0 = W[n * DD + k];
        float v1 = W[n * DD + k + 1];
        __nv_bfloat16 h0 = __float2bfloat16(v0), h1 = __float2bfloat16(v1);
        g_Bfrag_hi[idx] = ((uint32_t)__bfloat16_as_ushort(h1) << 16) | __bfloat16_as_ushort(h0);
        g_Bfrag_lo[idx] = ((uint32_t)bfu(v1 - __bfloat162float(h1)) << 16) | bfu(v0 - __bfloat162float(h0));
    }
    if (idx < NB) g_lb[idx] = 0ull;
    if (idx < NN) g_deg[idx] = 0;
}

// ---------------- histogram ----------------
__global__ void hist_kernel(const int* __restrict__ er) {
    int i = blockIdx.x * blockDim.x + threadIdx.x;
    if (i < NE) atomicAdd(&g_deg[er[i]], 1);
}

// ---------------- single-pass scan (decoupled lookback; 98 blocks, all resident) ----------------
__global__ void __launch_bounds__(256) scan_kernel() {
    __shared__ int sh[256];
    __shared__ int s_prefix;
    const int bid = blockIdx.x;
    const int tid = threadIdx.x;
    const int base = bid * 1024 + tid * 4;

    int vals[4];
    int s = 0;
#pragma unroll
    for (int k = 0; k < 4; k++) {
        int i = base + k;
        vals[k] = (i < NN) ? g_deg[i] : 0;
        s += vals[k];
    }
    sh[tid] = s;
    __syncthreads();
    for (int off = 1; off < 256; off <<= 1) {
        int t = (tid >= off) ? sh[tid - off] : 0;
        __syncthreads();
        sh[tid] += t;
        __syncthreads();
    }
    const int T = sh[255];                 // block total
    const int excl_local = sh[tid] - s;

    // publish aggregate (or prefix for block 0)
    if (tid == 0) {
        ull pub = ((bid == 0) ? (2ull << 32) : (1ull << 32)) | (unsigned)T;
        atomicExch(&g_lb[bid], pub);
        if (bid == 0) s_prefix = 0;
    }
    // warp 0 lookback
    if (bid > 0 && tid < 32) {
        int sum = 0;
        int wb = bid;
        while (true) {
            int idx = wb - 32 + tid;
            ull v;
            unsigned st;
            while (true) {
                v = (idx >= 0) ? atomicOr(&g_lb[idx], 0ull) : (2ull << 32);
                st = (unsigned)(v >> 32);
                if (__all_sync(0xffffffffu, st != 0)) break;
            }
            unsigned pmask = __ballot_sync(0xffffffffu, st == 2);
            if (pmask) {
                int lead = 31 - __clz(pmask);
                int c = (tid >= lead) ? (int)(v & 0xffffffffu) : 0;
#pragma unroll
                for (int o = 16; o; o >>= 1) c += __shfl_down_sync(0xffffffffu, c, o);
                if (tid == 0) sum += c;
                break;
            } else {
                int c = (int)(v & 0xffffffffu);
#pragma unroll
                for (int o = 16; o; o >>= 1) c += __shfl_down_sync(0xffffffffu, c, o);
                if (tid == 0) sum += c;
                wb -= 32;
            }
        }
        if (tid == 0) {
            s_prefix = sum;
            atomicExch(&g_lb[bid], (2ull << 32) | (unsigned)(sum + T));
        }
    }
    __syncthreads();

    int excl = excl_local + s_prefix;
#pragma unroll
    for (int k = 0; k < 4; k++) {
        int i = base + k;
        if (i < NN) { g_off[i] = excl; g_cur[i] = excl; }
        excl += vals[k];
    }
    if (bid == NB - 1 && tid == 255) g_off[NN] = excl;
}

// ---------------- permute edges into CSR order ----------------
__global__ void permute_kernel(const int* __restrict__ er, const int* __restrict__ ec) {
    int e = blockIdx.x * blockDim.x + threadIdx.x;
    if (e < NE) {
        int pos = atomicAdd(&g_cur[er[e]], 1);
        g_col[pos] = ec[e];
    }
}

// ---------------- GEMM: h = x @ W.T + b via HMMA (3-term bf16 split) ----------------
__device__ __forceinline__ void mma_bf16(float* c, const uint32_t* a, uint32_t b0, uint32_t b1) {
    asm volatile(
        "mma.sync.aligned.m16n8k16.row.col.f32.bf16.bf16.f32 "
        "{%0,%1,%2,%3}, {%4,%5,%6,%7}, {%8,%9}, {%0,%1,%2,%3};"
        : "+f"(c[0]), "+f"(c[1]), "+f"(c[2]), "+f"(c[3])
        : "r"(a[0]), "r"(a[1]), "r"(a[2]), "r"(a[3]), "r"(b0), "r"(b1));
}
__device__ __forceinline__ void ldm_x4(uint32_t* a, uint32_t addr) {
    asm volatile("ldmatrix.sync.aligned.m8n8.x4.shared.b16 {%0,%1,%2,%3}, [%4];"
                 : "=r"(a[0]), "=r"(a[1]), "=r"(a[2]), "=r"(a[3]) : "r"(addr));
}

#define GSMEM (2 * 128 * ROWPAD * 2)   // A_hi + A_lo, 69632 B

__global__ void __launch_bounds__(256) gemm_mma_kernel(const float* __restrict__ X,
                                                       const float* __restrict__ Bias) {
    extern __shared__ char smem[];
    __nv_bfloat16* Ah = (__nv_bfloat16*)smem;
    __nv_bfloat16* Al = (__nv_bfloat16*)(smem + 128 * ROWPAD * 2);

    const int tid = threadIdx.x;
    const int w = tid >> 5;
    const int lane = tid & 31;
    const int r0 = blockIdx.x * 128;

    // ---- load X tile, split-convert to hi/lo bf16 in SMEM ----
#pragma unroll
    for (int it = 0; it < 16; it++) {
        int idx = tid + it * 256;          // 4096 float4
        int row = idx >> 5;
        int kq  = idx & 31;
        float4 v = make_float4(0.f, 0.f, 0.f, 0.f);
        if (r0 + row < NN) v = *(const float4*)(X + (size_t)(r0 + row) * DD + kq * 4);
        __nv_bfloat16 hx = __float2bfloat16(v.x), hy = __float2bfloat16(v.y);
        __nv_bfloat16 hz = __float2bfloat16(v.z), hw = __float2bfloat16(v.w);
        uint32_t hi01 = ((uint32_t)__bfloat16_as_ushort(hy) << 16) | __bfloat16_as_ushort(hx);
        uint32_t hi23 = ((uint32_t)__bfloat16_as_ushort(hw) << 16) | __bfloat16_as_ushort(hz);
        uint32_t lo01 = ((uint32_t)bfu(v.y - __bfloat162float(hy)) << 16) | bfu(v.x - __bfloat162float(hx));
        uint32_t lo23 = ((uint32_t)bfu(v.w - __bfloat162float(hw)) << 16) | bfu(v.z - __bfloat162float(hz));
        *(ull*)(Ah + row * ROWPAD + kq * 4) = ((ull)hi23 << 32) | hi01;
        *(ull*)(Al + row * ROWPAD + kq * 4) = ((ull)lo23 << 32) | lo01;
    }

    // ---- resident B fragments (warp w owns cols 16w..16w+15) ----
    uint32_t bh[2][8][2], bl[2][8][2];
#pragma unroll
    for (int t = 0; t < 2; t++)
#pragma unroll
        for (int ks = 0; ks < 8; ks++)
#pragma unroll
            for (int r = 0; r < 2; r++) {
                int gi = (((2 * w + t) * 8 + ks) * 2 + r) * 32 + lane;
                bh[t][ks][r] = g_Bfrag_hi[gi];
                bl[t][ks][r] = g_Bfrag_lo[gi];
            }

    const int t2 = lane & 3;
    const int g  = lane >> 2;
    float2 bias0 = *(const float2*)(Bias + w * 16 + t2 * 2);
    float2 bias1 = *(const float2*)(Bias + w * 16 + 8 + t2 * 2);

    __syncthreads();

    const uint32_t ah_base = smem_u32(Ah);
    const uint32_t al_base = smem_u32(Al);
    const uint32_t rowoff =
        ((((lane >> 3) & 1) * 8 + (lane & 7)) * ROWPAD + (lane >> 4) * 8) * 2;

#pragma unroll
    for (int mt = 0; mt < 8; mt++) {
        float acc0[4] = {0.f, 0.f, 0.f, 0.f};
        float acc1[4] = {0.f, 0.f, 0.f, 0.f};
#pragma unroll
        for (int ks = 0; ks < 8; ks++) {
            uint32_t off = (uint32_t)(mt * 16 * ROWPAD * 2 + ks * 32) + rowoff;
            uint32_t ah[4], al[4];
            ldm_x4(ah, ah_base + off);
            ldm_x4(al, al_base + off);
            mma_bf16(acc0, ah, bh[0][ks][0], bh[0][ks][1]);
            mma_bf16(acc1, ah, bh[1][ks][0], bh[1][ks][1]);
            mma_bf16(acc0, ah, bl[0][ks][0], bl[0][ks][1]);
            mma_bf16(acc1, ah, bl[1][ks][0], bl[1][ks][1]);
            mma_bf16(acc0, al, bh[0][ks][0], bh[0][ks][1]);
            mma_bf16(acc1, al, bh[1][ks][0], bh[1][ks][1]);
        }
        int row = r0 + mt * 16 + g;
        int col0 = w * 16 + t2 * 2;
        if (row < NN) {
            float2 o0 = make_float2(acc0[0] + bias0.x, acc0[1] + bias0.y);
            float2 o1 = make_float2(acc1[0] + bias1.x, acc1[1] + bias1.y);
            float* p = g_h + (size_t)row * DD;
            *(float2*)(p + col0)     = o0;
            *(float2*)(p + col0 + 8) = o1;
            __half* q = g_hf + (size_t)row * DD;
            *(__half2*)(q + col0)     = __float22half2_rn(o0);
            *(__half2*)(q + col0 + 8) = __float22half2_rn(o1);
        }
        if (row + 8 < NN) {
            float2 o0 = make_float2(acc0[2] + bias0.x, acc0[3] + bias0.y);
            float2 o1 = make_float2(acc1[2] + bias1.x, acc1[3] + bias1.y);
            float* p = g_h + (size_t)(row + 8) * DD;
            *(float2*)(p + col0)     = o0;
            *(float2*)(p + col0 + 8) = o1;
            __half* q = g_hf + (size_t)(row + 8) * DD;
            *(__half2*)(q + col0)     = __float22half2_rn(o0);
            *(__half2*)(q + col0 + 8) = __float22half2_rn(o1);
        }
    }
}

// ---------------- gather: out[i] = relu( (h[i] + sum_j hf[col_j]) / (deg+1) ) ----------------
__device__ __forceinline__ void acc_half4(float4& acc, const __half* rowp, int lane) {
    uint2 r = *(const uint2*)(rowp + lane * 4);
    __half2 p0 = *(__half2*)&r.x;
    __half2 p1 = *(__half2*)&r.y;
    float2 f0 = __half22float2(p0);
    float2 f1 = __half22float2(p1);
    acc.x += f0.x; acc.y += f0.y; acc.z += f1.x; acc.w += f1.y;
}

__global__ void __launch_bounds__(256) gather_kernel(float* __restrict__ out) {
    int warp = (blockIdx.x * 256 + threadIdx.x) >> 5;
    int lane = threadIdx.x & 31;
    if (warp >= NN) return;
    int beg = g_off[warp];
    int end = g_off[warp + 1];

    // self-loop in fp32
    float4 acc = *(const float4*)(g_h + (size_t)warp * DD + lane * 4);

    int e = beg;
    for (; e + 4 <= end; e += 4) {
        int c0 = g_col[e + 0];
        int c1 = g_col[e + 1];
        int c2 = g_col[e + 2];
        int c3 = g_col[e + 3];
        acc_half4(acc, g_hf + (size_t)c0 * DD, lane);
        acc_half4(acc, g_hf + (size_t)c1 * DD, lane);
        acc_half4(acc, g_hf + (size_t)c2 * DD, lane);
        acc_half4(acc, g_hf + (size_t)c3 * DD, lane);
    }
    for (; e < end; e++) {
        acc_half4(acc, g_hf + (size_t)g_col[e] * DD, lane);
    }

    float inv = 1.0f / (float)(end - beg + 1);
    acc.x = fmaxf(acc.x * inv, 0.f);
    acc.y = fmaxf(acc.y * inv, 0.f);
    acc.z = fmaxf(acc.z * inv, 0.f);
    acc.w = fmaxf(acc.w * inv, 0.f);
    *(float4*)(out + (size_t)warp * DD + lane * 4) = acc;
}

extern "C" void kernel_launch(void* const* d_in, const int* in_sizes, int n_in,
                              void* d_out, int out_size) {
    const float* x  = (const float*)d_in[0];
    const float* W  = (const float*)d_in[1];
    const float* b  = (const float*)d_in[2];
    const int* er   = (const int*)d_in[3];
    const int* ec   = (const int*)d_in[4];
    float* out      = (float*)d_out;

    prep_kernel<<<(NN + 255) / 256, 256>>>(W);
    hist_kernel<<<(NE + 255) / 256, 256>>>(er);
    scan_kernel<<<NB, 256>>>();
    permute_kernel<<<(NE + 255) / 256, 256>>>(er, ec);

    cudaFuncSetAttribute(gemm_mma_kernel, cudaFuncAttributeMaxDynamicSharedMemorySize, GSMEM);
    gemm_mma_kernel<<<NTILE, 256, GSMEM>>>(x, b);

    gather_kernel<<<(NN * 32 + 255) / 256, 256>>>(out);
}

// round 6
// speedup vs baseline: 2.8891x; 1.1391x over previous
#include <cuda_runtime.h>
#include <cuda_bf16.h>
#include <cuda_fp16.h>
#include <cstdint>

#define NN 100000
#define NE 1600000
#define DD 128
#define NB ((NN + 1023) / 1024)     // 98 scan blocks
#define NTILE ((NN + 127) / 128)    // 782 GEMM tiles
#define NHIST ((NE + 1023) / 1024)  // 1563 hist blocks (ILP4)
#define ROWPAD 136                  // bf16 elems per SMEM row (272B, conflict-free)

typedef unsigned long long ull;

// ---------------- scratch (__device__ globals; no allocation allowed) ----------------
__device__ __half g_hf[(size_t)NN * DD];   // 25.6 MB fp16 h = x @ W.T + b
__device__ int    g_deg[NN];
__device__ int    g_off[NN + 1];
__device__ int    g_cur[NN];
__device__ int    g_col[NE];
__device__ ull    g_lb[NB];                // lookback state: (state<<32)|value
// Pre-fragmented W for mma.sync: [nt(16)][ks(8)][r(2)][lane(32)] uint32 (b16 pairs)
__device__ uint32_t g_Bfrag_hi[8192];
__device__ uint32_t g_Bfrag_lo[8192];

__device__ __forceinline__ uint32_t smem_u32(const void* p) {
    uint32_t a;
    asm("{ .reg .u64 t; cvta.to.shared.u64 t, %1; cvt.u32.u64 %0, t; }" : "=r"(a) : "l"(p));
    return a;
}
__device__ __forceinline__ unsigned short bfu(float v) {
    return __bfloat16_as_ushort(__float2bfloat16(v));
}

// ---------------- prep: W fragments + zero deg + zero lookback ----------------
__global__ void prep_kernel(const float* __restrict__ W) {
    int idx = blockIdx.x * blockDim.x + threadIdx.x;
    if (idx < 8192) {
        int lane = idx & 31;
        int r    = (idx >> 5) & 1;
        int ks   = (idx >> 6) & 7;
        int nt   = idx >> 9;
        int n = nt * 8 + (lane >> 2);
        int k = ks * 16 + r * 8 + (lane & 3) * 2;
        float v0 = W[n * DD + k];
        float v1 = W[n * DD + k + 1];
        __nv_bfloat16 h0 = __float2bfloat16(v0), h1 = __float2bfloat16(v1);
        g_Bfrag_hi[idx] = ((uint32_t)__bfloat16_as_ushort(h1) << 16) | __bfloat16_as_ushort(h0);
        g_Bfrag_lo[idx] = ((uint32_t)bfu(v1 - __bfloat162float(h1)) << 16) | bfu(v0 - __bfloat162float(h0));
    }
    if (idx < NB) g_lb[idx] = 0ull;
    if (idx < NN) g_deg[idx] = 0;
}

// ---------------- HMMA helpers ----------------
__device__ __forceinline__ void mma_bf16(float* c, const uint32_t* a, uint32_t b0, uint32_t b1) {
    asm volatile(
        "mma.sync.aligned.m16n8k16.row.col.f32.bf16.bf16.f32 "
        "{%0,%1,%2,%3}, {%4,%5,%6,%7}, {%8,%9}, {%0,%1,%2,%3};"
        : "+f"(c[0]), "+f"(c[1]), "+f"(c[2]), "+f"(c[3])
        : "r"(a[0]), "r"(a[1]), "r"(a[2]), "r"(a[3]), "r"(b0), "r"(b1));
}
__device__ __forceinline__ void ldm_x4(uint32_t* a, uint32_t addr) {
    asm volatile("ldmatrix.sync.aligned.m8n8.x4.shared.b16 {%0,%1,%2,%3}, [%4];"
                 : "=r"(a[0]), "=r"(a[1]), "=r"(a[2]), "=r"(a[3]) : "r"(addr));
}

#define GSMEM (2 * 128 * ROWPAD * 2)   // A_hi + A_lo, 69632 B

// ---------------- fused: GEMM tiles (blocks 0..NTILE-1) + histogram (rest) ----------------
__global__ void __launch_bounds__(256) gemm_hist_kernel(const float* __restrict__ X,
                                                        const float* __restrict__ Bias,
                                                        const int* __restrict__ er) {
    const int tid = threadIdx.x;

    if (blockIdx.x >= NTILE) {
        // ---- histogram part: 4 edges per thread ----
        int base = (blockIdx.x - NTILE) * 1024 + tid * 4;
        if (base + 3 < NE) {
            int4 r4 = *(const int4*)(er + base);
            atomicAdd(&g_deg[r4.x], 1);
            atomicAdd(&g_deg[r4.y], 1);
            atomicAdd(&g_deg[r4.z], 1);
            atomicAdd(&g_deg[r4.w], 1);
        } else {
            for (int e = base; e < NE; e++) atomicAdd(&g_deg[er[e]], 1);
        }
        return;
    }

    // ---- GEMM part ----
    extern __shared__ char smem[];
    __nv_bfloat16* Ah = (__nv_bfloat16*)smem;
    __nv_bfloat16* Al = (__nv_bfloat16*)(smem + 128 * ROWPAD * 2);

    const int w = tid >> 5;
    const int lane = tid & 31;
    const int r0 = blockIdx.x * 128;

    // load X tile, split-convert to hi/lo bf16 in SMEM
#pragma unroll
    for (int it = 0; it < 16; it++) {
        int idx = tid + it * 256;          // 4096 float4
        int row = idx >> 5;
        int kq  = idx & 31;
        float4 v = make_float4(0.f, 0.f, 0.f, 0.f);
        if (r0 + row < NN) v = *(const float4*)(X + (size_t)(r0 + row) * DD + kq * 4);
        __nv_bfloat16 hx = __float2bfloat16(v.x), hy = __float2bfloat16(v.y);
        __nv_bfloat16 hz = __float2bfloat16(v.z), hw = __float2bfloat16(v.w);
        uint32_t hi01 = ((uint32_t)__bfloat16_as_ushort(hy) << 16) | __bfloat16_as_ushort(hx);
        uint32_t hi23 = ((uint32_t)__bfloat16_as_ushort(hw) << 16) | __bfloat16_as_ushort(hz);
        uint32_t lo01 = ((uint32_t)bfu(v.y - __bfloat162float(hy)) << 16) | bfu(v.x - __bfloat162float(hx));
        uint32_t lo23 = ((uint32_t)bfu(v.w - __bfloat162float(hw)) << 16) | bfu(v.z - __bfloat162float(hz));
        *(ull*)(Ah + row * ROWPAD + kq * 4) = ((ull)hi23 << 32) | hi01;
        *(ull*)(Al + row * ROWPAD + kq * 4) = ((ull)lo23 << 32) | lo01;
    }

    // resident B fragments (warp w owns cols 16w..16w+15)
    uint32_t bh[2][8][2], bl[2][8][2];
#pragma unroll
    for (int t = 0; t < 2; t++)
#pragma unroll
        for (int ks = 0; ks < 8; ks++)
#pragma unroll
            for (int r = 0; r < 2; r++) {
                int gi = (((2 * w + t) * 8 + ks) * 2 + r) * 32 + lane;
                bh[t][ks][r] = g_Bfrag_hi[gi];
                bl[t][ks][r] = g_Bfrag_lo[gi];
            }

    const int t2 = lane & 3;
    const int g  = lane >> 2;
    float2 bias0 = *(const float2*)(Bias + w * 16 + t2 * 2);
    float2 bias1 = *(const float2*)(Bias + w * 16 + 8 + t2 * 2);

    __syncthreads();

    const uint32_t ah_base = smem_u32(Ah);
    const uint32_t al_base = smem_u32(Al);
    const uint32_t rowoff =
        ((((lane >> 3) & 1) * 8 + (lane & 7)) * ROWPAD + (lane >> 4) * 8) * 2;

#pragma unroll
    for (int mt = 0; mt < 8; mt++) {
        float acc0[4] = {0.f, 0.f, 0.f, 0.f};
        float acc1[4] = {0.f, 0.f, 0.f, 0.f};
#pragma unroll
        for (int ks = 0; ks < 8; ks++) {
            uint32_t off = (uint32_t)(mt * 16 * ROWPAD * 2 + ks * 32) + rowoff;
            uint32_t ah[4], al[4];
            ldm_x4(ah, ah_base + off);
            ldm_x4(al, al_base + off);
            mma_bf16(acc0, ah, bh[0][ks][0], bh[0][ks][1]);
            mma_bf16(acc1, ah, bh[1][ks][0], bh[1][ks][1]);
            mma_bf16(acc0, ah, bl[0][ks][0], bl[0][ks][1]);
            mma_bf16(acc1, ah, bl[1][ks][0], bl[1][ks][1]);
            mma_bf16(acc0, al, bh[0][ks][0], bh[0][ks][1]);
            mma_bf16(acc1, al, bh[1][ks][0], bh[1][ks][1]);
        }
        int row = r0 + mt * 16 + g;
        int col0 = w * 16 + t2 * 2;
        if (row < NN) {
            __half* q = g_hf + (size_t)row * DD;
            *(__half2*)(q + col0) =
                __float22half2_rn(make_float2(acc0[0] + bias0.x, acc0[1] + bias0.y));
            *(__half2*)(q + col0 + 8) =
                __float22half2_rn(make_float2(acc1[0] + bias1.x, acc1[1] + bias1.y));
        }
        if (row + 8 < NN) {
            __half* q = g_hf + (size_t)(row + 8) * DD;
            *(__half2*)(q + col0) =
                __float22half2_rn(make_float2(acc0[2] + bias0.x, acc0[3] + bias0.y));
            *(__half2*)(q + col0 + 8) =
                __float22half2_rn(make_float2(acc1[2] + bias1.x, acc1[3] + bias1.y));
        }
    }
}

// ---------------- single-pass scan (decoupled lookback; 98 blocks, all resident) ----------------
__global__ void __launch_bounds__(256) scan_kernel() {
    __shared__ int sh[256];
    __shared__ int s_prefix;
    const int bid = blockIdx.x;
    const int tid = threadIdx.x;
    const int base = bid * 1024 + tid * 4;

    int vals[4];
    int s = 0;
#pragma unroll
    for (int k = 0; k < 4; k++) {
        int i = base + k;
        vals[k] = (i < NN) ? g_deg[i] : 0;
        s += vals[k];
    }
    sh[tid] = s;
    __syncthreads();
    for (int off = 1; off < 256; off <<= 1) {
        int t = (tid >= off) ? sh[tid - off] : 0;
        __syncthreads();
        sh[tid] += t;
        __syncthreads();
    }
    const int T = sh[255];
    const int excl_local = sh[tid] - s;

    if (tid == 0) {
        ull pub = ((bid == 0) ? (2ull << 32) : (1ull << 32)) | (unsigned)T;
        atomicExch(&g_lb[bid], pub);
        if (bid == 0) s_prefix = 0;
    }
    if (bid > 0 && tid < 32) {
        int sum = 0;
        int wb = bid;
        while (true) {
            int idx = wb - 32 + tid;
            ull v;
            unsigned st;
            while (true) {
                v = (idx >= 0) ? atomicOr(&g_lb[idx], 0ull) : (2ull << 32);
                st = (unsigned)(v >> 32);
                if (__all_sync(0xffffffffu, st != 0)) break;
            }
            unsigned pmask = __ballot_sync(0xffffffffu, st == 2);
            if (pmask) {
                int lead = 31 - __clz(pmask);
                int c = (tid >= lead) ? (int)(v & 0xffffffffu) : 0;
#pragma unroll
                for (int o = 16; o; o >>= 1) c += __shfl_down_sync(0xffffffffu, c, o);
                if (tid == 0) sum += c;
                break;
            } else {
                int c = (int)(v & 0xffffffffu);
#pragma unroll
                for (int o = 16; o; o >>= 1) c += __shfl_down_sync(0xffffffffu, c, o);
                if (tid == 0) sum += c;
                wb -= 32;
            }
        }
        if (tid == 0) {
            s_prefix = sum;
            atomicExch(&g_lb[bid], (2ull << 32) | (unsigned)(sum + T));
        }
    }
    __syncthreads();

    int excl = excl_local + s_prefix;
#pragma unroll
    for (int k = 0; k < 4; k++) {
        int i = base + k;
        if (i < NN) { g_off[i] = excl; g_cur[i] = excl; }
        excl += vals[k];
    }
    if (bid == NB - 1 && tid == 255) g_off[NN] = excl;
}

// ---------------- permute edges into CSR order (4 edges/thread) ----------------
__global__ void __launch_bounds__(256) permute_kernel(const int* __restrict__ er,
                                                      const int* __restrict__ ec) {
    int base = (blockIdx.x * 256 + threadIdx.x) * 4;
    if (base + 3 < NE) {
        int4 r4 = *(const int4*)(er + base);
        int4 c4 = *(const int4*)(ec + base);
        int p0 = atomicAdd(&g_cur[r4.x], 1);
        int p1 = atomicAdd(&g_cur[r4.y], 1);
        int p2 = atomicAdd(&g_cur[r4.z], 1);
        int p3 = atomicAdd(&g_cur[r4.w], 1);
        g_col[p0] = c4.x;
        g_col[p1] = c4.y;
        g_col[p2] = c4.z;
        g_col[p3] = c4.w;
    } else {
        for (int e = base; e < NE; e++) {
            int pos = atomicAdd(&g_cur[er[e]], 1);
            g_col[pos] = ec[e];
        }
    }
}

// ---------------- gather: out[i] = relu( (hf[i] + sum_j hf[col_j]) / (deg+1) ) ----------------
__device__ __forceinline__ void acc_half4(float4& acc, const __half* rowp, int lane) {
    uint2 r = *(const uint2*)(rowp + lane * 4);
    __half2 p0 = *(__half2*)&r.x;
    __half2 p1 = *(__half2*)&r.y;
    float2 f0 = __half22float2(p0);
    float2 f1 = __half22float2(p1);
    acc.x += f0.x; acc.y += f0.y; acc.z += f1.x; acc.w += f1.y;
}

__global__ void __launch_bounds__(256) gather_kernel(float* __restrict__ out) {
    int warp = (blockIdx.x * 256 + threadIdx.x) >> 5;
    int lane = threadIdx.x & 31;
    if (warp >= NN) return;
    int beg = g_off[warp];
    int end = g_off[warp + 1];

    float4 acc = make_float4(0.f, 0.f, 0.f, 0.f);
    acc_half4(acc, g_hf + (size_t)warp * DD, lane);   // self-loop

    int e = beg;
    for (; e + 4 <= end; e += 4) {
        int c0 = g_col[e + 0];
        int c1 = g_col[e + 1];
        int c2 = g_col[e + 2];
        int c3 = g_col[e + 3];
        acc_half4(acc, g_hf + (size_t)c0 * DD, lane);
        acc_half4(acc, g_hf + (size_t)c1 * DD, lane);
        acc_half4(acc, g_hf + (size_t)c2 * DD, lane);
        acc_half4(acc, g_hf + (size_t)c3 * DD, lane);
    }
    for (; e < end; e++) {
        acc_half4(acc, g_hf + (size_t)g_col[e] * DD, lane);
    }

    float inv = 1.0f / (float)(end - beg + 1);
    acc.x = fmaxf(acc.x * inv, 0.f);
    acc.y = fmaxf(acc.y * inv, 0.f);
    acc.z = fmaxf(acc.z * inv, 0.f);
    acc.w = fmaxf(acc.w * inv, 0.f);
    *(float4*)(out + (size_t)warp * DD + lane * 4) = acc;
}

extern "C" void kernel_launch(void* const* d_in, const int* in_sizes, int n_in,
                              void* d_out, int out_size) {
    const float* x  = (const float*)d_in[0];
    const float* W  = (const float*)d_in[1];
    const float* b  = (const float*)d_in[2];
    const int* er   = (const int*)d_in[3];
    const int* ec   = (const int*)d_in[4];
    float* out      = (float*)d_out;

    prep_kernel<<<(NN + 255) / 256, 256>>>(W);

    cudaFuncSetAttribute(gemm_hist_kernel, cudaFuncAttributeMaxDynamicSharedMemorySize, GSMEM);
    gemm_hist_kernel<<<NTILE + NHIST, 256, GSMEM>>>(x, b, er);

    scan_kernel<<<NB, 256>>>();
    permute_kernel<<<(NE / 4 + 255) / 256, 256>>>(er, ec);
    gather_kernel<<<(NN * 32 + 255) / 256, 256>>>(out);
}

// round 7
// speedup vs baseline: 2.9646x; 1.0261x over previous
#include <cuda_runtime.h>
#include <cuda_bf16.h>
#include <cuda_fp16.h>
#include <cstdint>

#define NN 100000
#define NE 1600000
#define DD 128
#define NB ((NN + 1023) / 1024)       // 98 scan blocks
#define NTILE ((NN + 127) / 128)      // 782 GEMM tiles
#define NPERM ((NE + 2047) / 2048)    // 782 permute blocks (ILP8)
#define NHIST ((NE + 2047) / 2048)    // 782 hist blocks (ILP8)
#define ROWPAD 136                    // bf16 elems per SMEM row (272B, conflict-free)

typedef unsigned long long ull;

// ---------------- scratch (__device__ globals; zero-initialized at load) ----------------
__device__ __half g_hf[(size_t)NN * DD];   // 25.6 MB fp16 h = x @ W.T + b
__device__ int    g_deg[NN];               // invariant: 0 at kernel_launch entry
__device__ int    g_off[NN + 1];
__device__ int    g_cur[NN];
__device__ int    g_col[NE];
__device__ ull    g_lb[NB];                // lookback state: (state<<32)|value
// Pre-fragmented W for mma.sync: [nt(16)][ks(8)][r(2)][lane(32)] uint32 (b16 pairs)
__device__ uint32_t g_Bfrag_hi[8192];
__device__ uint32_t g_Bfrag_lo[8192];

__device__ __forceinline__ uint32_t smem_u32(const void* p) {
    uint32_t a;
    asm("{ .reg .u64 t; cvta.to.shared.u64 t, %1; cvt.u32.u64 %0, t; }" : "=r"(a) : "l"(p));
    return a;
}
__device__ __forceinline__ unsigned short bfu(float v) {
    return __bfloat16_as_ushort(__float2bfloat16(v));
}

// ---------------- launch 1: W fragments + zero-lb (blocks 0..31) | histogram (rest) ----------------
__global__ void __launch_bounds__(256) hist_prep_kernel(const int* __restrict__ er,
                                                        const float* __restrict__ W) {
    const int tid = threadIdx.x;
    if (blockIdx.x < 32) {
        int idx = blockIdx.x * 256 + tid;          // 0..8191
        int lane = idx & 31;
        int r    = (idx >> 5) & 1;
        int ks   = (idx >> 6) & 7;
        int nt   = idx >> 9;
        int n = nt * 8 + (lane >> 2);
        int k = ks * 16 + r * 8 + (lane & 3) * 2;
        float v0 = W[n * DD + k];
        float v1 = W[n * DD + k + 1];
        __nv_bfloat16 h0 = __float2bfloat16(v0), h1 = __float2bfloat16(v1);
        g_Bfrag_hi[idx] = ((uint32_t)__bfloat16_as_ushort(h1) << 16) | __bfloat16_as_ushort(h0);
        g_Bfrag_lo[idx] = ((uint32_t)bfu(v1 - __bfloat162float(h1)) << 16) | bfu(v0 - __bfloat162float(h0));
        if (idx < NB) g_lb[idx] = 0ull;
        return;
    }
    // histogram: 8 edges per thread
    int base = (blockIdx.x - 32) * 2048 + tid * 8;
    if (base + 7 < NE) {
        int4 a = *(const int4*)(er + base);
        int4 c = *(const int4*)(er + base + 4);
        atomicAdd(&g_deg[a.x], 1);
        atomicAdd(&g_deg[a.y], 1);
        atomicAdd(&g_deg[a.z], 1);
        atomicAdd(&g_deg[a.w], 1);
        atomicAdd(&g_deg[c.x], 1);
        atomicAdd(&g_deg[c.y], 1);
        atomicAdd(&g_deg[c.z], 1);
        atomicAdd(&g_deg[c.w], 1);
    } else {
        for (int e = base; e < NE; e++) atomicAdd(&g_deg[e < NE ? er[e] : 0], 1);
    }
}

// ---------------- launch 2: single-pass scan (decoupled lookback) + deg reset ----------------
__global__ void __launch_bounds__(256) scan_kernel() {
    __shared__ int sh[256];
    __shared__ int s_prefix;
    const int bid = blockIdx.x;
    const int tid = threadIdx.x;
    const int base = bid * 1024 + tid * 4;

    int vals[4];
    int s = 0;
#pragma unroll
    for (int k = 0; k < 4; k++) {
        int i = base + k;
        vals[k] = (i < NN) ? g_deg[i] : 0;
        if (i < NN) g_deg[i] = 0;          // restore invariant for next replay
        s += vals[k];
    }
    sh[tid] = s;
    __syncthreads();
    for (int off = 1; off < 256; off <<= 1) {
        int t = (tid >= off) ? sh[tid - off] : 0;
        __syncthreads();
        sh[tid] += t;
        __syncthreads();
    }
    const int T = sh[255];
    const int excl_local = sh[tid] - s;

    if (tid == 0) {
        ull pub = ((bid == 0) ? (2ull << 32) : (1ull << 32)) | (unsigned)T;
        atomicExch(&g_lb[bid], pub);
        if (bid == 0) s_prefix = 0;
    }
    if (bid > 0 && tid < 32) {
        int sum = 0;
        int wb = bid;
        while (true) {
            int idx = wb - 32 + tid;
            ull v;
            unsigned st;
            while (true) {
                v = (idx >= 0) ? atomicOr(&g_lb[idx], 0ull) : (2ull << 32);
                st = (unsigned)(v >> 32);
                if (__all_sync(0xffffffffu, st != 0)) break;
            }
            unsigned pmask = __ballot_sync(0xffffffffu, st == 2);
            if (pmask) {
                int lead = 31 - __clz(pmask);
                int c = (tid >= lead) ? (int)(v & 0xffffffffu) : 0;
#pragma unroll
                for (int o = 16; o; o >>= 1) c += __shfl_down_sync(0xffffffffu, c, o);
                if (tid == 0) sum += c;
                break;
            } else {
                int c = (int)(v & 0xffffffffu);
#pragma unroll
                for (int o = 16; o; o >>= 1) c += __shfl_down_sync(0xffffffffu, c, o);
                if (tid == 0) sum += c;
                wb -= 32;
            }
        }
        if (tid == 0) {
            s_prefix = sum;
            atomicExch(&g_lb[bid], (2ull << 32) | (unsigned)(sum + T));
        }
    }
    __syncthreads();

    int excl = excl_local + s_prefix;
#pragma unroll
    for (int k = 0; k < 4; k++) {
        int i = base + k;
        if (i < NN) { g_off[i] = excl; g_cur[i] = excl; }
        excl += vals[k];
    }
    if (bid == NB - 1 && tid == 255) g_off[NN] = excl;
}

// ---------------- HMMA helpers ----------------
__device__ __forceinline__ void mma_bf16(float* c, const uint32_t* a, uint32_t b0, uint32_t b1) {
    asm volatile(
        "mma.sync.aligned.m16n8k16.row.col.f32.bf16.bf16.f32 "
        "{%0,%1,%2,%3}, {%4,%5,%6,%7}, {%8,%9}, {%0,%1,%2,%3};"
        : "+f"(c[0]), "+f"(c[1]), "+f"(c[2]), "+f"(c[3])
        : "r"(a[0]), "r"(a[1]), "r"(a[2]), "r"(a[3]), "r"(b0), "r"(b1));
}
__device__ __forceinline__ void ldm_x4(uint32_t* a, uint32_t addr) {
    asm volatile("ldmatrix.sync.aligned.m8n8.x4.shared.b16 {%0,%1,%2,%3}, [%4];"
                 : "=r"(a[0]), "=r"(a[1]), "=r"(a[2]), "=r"(a[3]) : "r"(addr));
}

#define GSMEM (2 * 128 * ROWPAD * 2)   // A_hi + A_lo, 69632 B

// ---------------- launch 3: GEMM tiles (blocks 0..NTILE-1) + permute (rest) ----------------
__global__ void __launch_bounds__(256) gemm_perm_kernel(const float* __restrict__ X,
                                                        const float* __restrict__ Bias,
                                                        const int* __restrict__ er,
                                                        const int* __restrict__ ec) {
    const int tid = threadIdx.x;

    if (blockIdx.x >= NTILE) {
        // ---- permute: 8 edges per thread ----
        int base = (blockIdx.x - NTILE) * 2048 + tid * 8;
        if (base + 7 < NE) {
            int4 r0 = *(const int4*)(er + base);
            int4 r1 = *(const int4*)(er + base + 4);
            int4 c0 = *(const int4*)(ec + base);
            int4 c1 = *(const int4*)(ec + base + 4);
            int p0 = atomicAdd(&g_cur[r0.x], 1);
            int p1 = atomicAdd(&g_cur[r0.y], 1);
            int p2 = atomicAdd(&g_cur[r0.z], 1);
            int p3 = atomicAdd(&g_cur[r0.w], 1);
            int p4 = atomicAdd(&g_cur[r1.x], 1);
            int p5 = atomicAdd(&g_cur[r1.y], 1);
            int p6 = atomicAdd(&g_cur[r1.z], 1);
            int p7 = atomicAdd(&g_cur[r1.w], 1);
            g_col[p0] = c0.x; g_col[p1] = c0.y; g_col[p2] = c0.z; g_col[p3] = c0.w;
            g_col[p4] = c1.x; g_col[p5] = c1.y; g_col[p6] = c1.z; g_col[p7] = c1.w;
        } else {
            for (int e = base; e < NE; e++) {
                int pos = atomicAdd(&g_cur[er[e]], 1);
                g_col[pos] = ec[e];
            }
        }
        return;
    }

    // ---- GEMM part ----
    extern __shared__ char smem[];
    __nv_bfloat16* Ah = (__nv_bfloat16*)smem;
    __nv_bfloat16* Al = (__nv_bfloat16*)(smem + 128 * ROWPAD * 2);

    const int w = tid >> 5;
    const int lane = tid & 31;
    const int r0 = blockIdx.x * 128;

#pragma unroll
    for (int it = 0; it < 16; it++) {
        int idx = tid + it * 256;          // 4096 float4
        int row = idx >> 5;
        int kq  = idx & 31;
        float4 v = make_float4(0.f, 0.f, 0.f, 0.f);
        if (r0 + row < NN) v = *(const float4*)(X + (size_t)(r0 + row) * DD + kq * 4);
        __nv_bfloat16 hx = __float2bfloat16(v.x), hy = __float2bfloat16(v.y);
        __nv_bfloat16 hz = __float2bfloat16(v.z), hw = __float2bfloat16(v.w);
        uint32_t hi01 = ((uint32_t)__bfloat16_as_ushort(hy) << 16) | __bfloat16_as_ushort(hx);
        uint32_t hi23 = ((uint32_t)__bfloat16_as_ushort(hw) << 16) | __bfloat16_as_ushort(hz);
        uint32_t lo01 = ((uint32_t)bfu(v.y - __bfloat162float(hy)) << 16) | bfu(v.x - __bfloat162float(hx));
        uint32_t lo23 = ((uint32_t)bfu(v.w - __bfloat162float(hw)) << 16) | bfu(v.z - __bfloat162float(hz));
        *(ull*)(Ah + row * ROWPAD + kq * 4) = ((ull)hi23 << 32) | hi01;
        *(ull*)(Al + row * ROWPAD + kq * 4) = ((ull)lo23 << 32) | lo01;
    }

    uint32_t bh[2][8][2], bl[2][8][2];
#pragma unroll
    for (int t = 0; t < 2; t++)
#pragma unroll
        for (int ks = 0; ks < 8; ks++)
#pragma unroll
            for (int r = 0; r < 2; r++) {
                int gi = (((2 * w + t) * 8 + ks) * 2 + r) * 32 + lane;
                bh[t][ks][r] = g_Bfrag_hi[gi];
                bl[t][ks][r] = g_Bfrag_lo[gi];
            }

    const int t2 = lane & 3;
    const int g  = lane >> 2;
    float2 bias0 = *(const float2*)(Bias + w * 16 + t2 * 2);
    float2 bias1 = *(const float2*)(Bias + w * 16 + 8 + t2 * 2);

    __syncthreads();

    const uint32_t ah_base = smem_u32(Ah);
    const uint32_t al_base = smem_u32(Al);
    const uint32_t rowoff =
        ((((lane >> 3) & 1) * 8 + (lane & 7)) * ROWPAD + (lane >> 4) * 8) * 2;

#pragma unroll
    for (int mt = 0; mt < 8; mt++) {
        float acc0[4] = {0.f, 0.f, 0.f, 0.f};
        float acc1[4] = {0.f, 0.f, 0.f, 0.f};
#pragma unroll
        for (int ks = 0; ks < 8; ks++) {
            uint32_t off = (uint32_t)(mt * 16 * ROWPAD * 2 + ks * 32) + rowoff;
            uint32_t ah[4], al[4];
            ldm_x4(ah, ah_base + off);
            ldm_x4(al, al_base + off);
            mma_bf16(acc0, ah, bh[0][ks][0], bh[0][ks][1]);
            mma_bf16(acc1, ah, bh[1][ks][0], bh[1][ks][1]);
            mma_bf16(acc0, ah, bl[0][ks][0], bl[0][ks][1]);
            mma_bf16(acc1, ah, bl[1][ks][0], bl[1][ks][1]);
            mma_bf16(acc0, al, bh[0][ks][0], bh[0][ks][1]);
            mma_bf16(acc1, al, bh[1][ks][0], bh[1][ks][1]);
        }
        int row = r0 + mt * 16 + g;
        int col0 = w * 16 + t2 * 2;
        if (row < NN) {
            __half* q = g_hf + (size_t)row * DD;
            *(__half2*)(q + col0) =
                __float22half2_rn(make_float2(acc0[0] + bias0.x, acc0[1] + bias0.y));
            *(__half2*)(q + col0 + 8) =
                __float22half2_rn(make_float2(acc1[0] + bias1.x, acc1[1] + bias1.y));
        }
        if (row + 8 < NN) {
            __half* q = g_hf + (size_t)(row + 8) * DD;
            *(__half2*)(q + col0) =
                __float22half2_rn(make_float2(acc0[2] + bias0.x, acc0[3] + bias0.y));
            *(__half2*)(q + col0 + 8) =
                __float22half2_rn(make_float2(acc1[2] + bias1.x, acc1[3] + bias1.y));
        }
    }
}

// ---------------- launch 4: gather ----------------
__device__ __forceinline__ void acc_half4(float4& acc, const __half* rowp, int lane) {
    uint2 r = *(const uint2*)(rowp + lane * 4);
    __half2 p0 = *(__half2*)&r.x;
    __half2 p1 = *(__half2*)&r.y;
    float2 f0 = __half22float2(p0);
    float2 f1 = __half22float2(p1);
    acc.x += f0.x; acc.y += f0.y; acc.z += f1.x; acc.w += f1.y;
}

__global__ void __launch_bounds__(256) gather_kernel(float* __restrict__ out) {
    int warp = (blockIdx.x * 256 + threadIdx.x) >> 5;
    int lane = threadIdx.x & 31;
    if (warp >= NN) return;
    int beg = g_off[warp];
    int end = g_off[warp + 1];

    float4 acc = make_float4(0.f, 0.f, 0.f, 0.f);
    acc_half4(acc, g_hf + (size_t)warp * DD, lane);   // self-loop

    int e = beg;
    for (; e + 4 <= end; e += 4) {
        int c0 = g_col[e + 0];
        int c1 = g_col[e + 1];
        int c2 = g_col[e + 2];
        int c3 = g_col[e + 3];
        acc_half4(acc, g_hf + (size_t)c0 * DD, lane);
        acc_half4(acc, g_hf + (size_t)c1 * DD, lane);
        acc_half4(acc, g_hf + (size_t)c2 * DD, lane);
        acc_half4(acc, g_hf + (size_t)c3 * DD, lane);
    }
    for (; e < end; e++) {
        acc_half4(acc, g_hf + (size_t)g_col[e] * DD, lane);
    }

    float inv = 1.0f / (float)(end - beg + 1);
    acc.x = fmaxf(acc.x * inv, 0.f);
    acc.y = fmaxf(acc.y * inv, 0.f);
    acc.z = fmaxf(acc.z * inv, 0.f);
    acc.w = fmaxf(acc.w * inv, 0.f);
    *(float4*)(out + (size_t)warp * DD + lane * 4) = acc;
}

extern "C" void kernel_launch(void* const* d_in, const int* in_sizes, int n_in,
                              void* d_out, int out_size) {
    const float* x  = (const float*)d_in[0];
    const float* W  = (const float*)d_in[1];
    const float* b  = (const float*)d_in[2];
    const int* er   = (const int*)d_in[3];
    const int* ec   = (const int*)d_in[4];
    float* out      = (float*)d_out;

    hist_prep_kernel<<<NHIST + 32, 256>>>(er, W);
    scan_kernel<<<NB, 256>>>();

    cudaFuncSetAttribute(gemm_perm_kernel, cudaFuncAttributeMaxDynamicSharedMemorySize, GSMEM);
    gemm_perm_kernel<<<NTILE + NPERM, 256, GSMEM>>>(x, b, er, ec);

    gather_kernel<<<(NN * 32 + 255) / 256, 256>>>(out);
}

// round 8
// speedup vs baseline: 2.9924x; 1.0094x over previous
#include <cuda_runtime.h>
#include <cuda_bf16.h>
#include <cuda_fp16.h>
#include <cstdint>

#define NN 100000
#define NE 1600000
#define DD 128
#define NB ((NN + 1023) / 1024)       // 98 scan blocks
#define NTILE ((NN + 127) / 128)      // 782 GEMM tiles
#define NTA 391                       // gemmA tiles (launch 2)
#define NTB (NTILE - NTA)             // gemmB tiles (launch 3)
#define NPERM ((NE + 2047) / 2048)    // 782 permute blocks (ILP8)
#define NHIST ((NE + 2047) / 2048)    // 782 hist blocks (ILP8)
#define ROWPAD 136                    // bf16 elems per SMEM row (272B, conflict-free)

typedef unsigned long long ull;

// ---------------- scratch (__device__ globals; zero-initialized at load) ----------------
__device__ __half g_hf[(size_t)NN * DD];   // 25.6 MB fp16 h = x @ W.T + b
__device__ int    g_deg[NN];               // invariant: 0 at kernel_launch entry
__device__ int    g_off[NN + 1];
__device__ int    g_cur[NN];
__device__ int    g_col[NE];
__device__ ull    g_lb[NB];                // lookback state: (state<<32)|value
// Pre-fragmented W for mma.sync: [nt(16)][ks(8)][r(2)][lane(32)] uint32 (b16 pairs)
__device__ uint32_t g_Bfrag_hi[8192];
__device__ uint32_t g_Bfrag_lo[8192];

__device__ __forceinline__ uint32_t smem_u32(const void* p) {
    uint32_t a;
    asm("{ .reg .u64 t; cvta.to.shared.u64 t, %1; cvt.u32.u64 %0, t; }" : "=r"(a) : "l"(p));
    return a;
}
__device__ __forceinline__ unsigned short bfu(float v) {
    return __bfloat16_as_ushort(__float2bfloat16(v));
}

// ---------------- launch 1: W fragments + zero-lb (blocks 0..31) | histogram (rest) ----------------
__global__ void __launch_bounds__(256) hist_prep_kernel(const int* __restrict__ er,
                                                        const float* __restrict__ W) {
    const int tid = threadIdx.x;
    if (blockIdx.x < 32) {
        int idx = blockIdx.x * 256 + tid;          // 0..8191
        int lane = idx & 31;
        int r    = (idx >> 5) & 1;
        int ks   = (idx >> 6) & 7;
        int nt   = idx >> 9;
        int n = nt * 8 + (lane >> 2);
        int k = ks * 16 + r * 8 + (lane & 3) * 2;
        float v0 = W[n * DD + k];
        float v1 = W[n * DD + k + 1];
        __nv_bfloat16 h0 = __float2bfloat16(v0), h1 = __float2bfloat16(v1);
        g_Bfrag_hi[idx] = ((uint32_t)__bfloat16_as_ushort(h1) << 16) | __bfloat16_as_ushort(h0);
        g_Bfrag_lo[idx] = ((uint32_t)bfu(v1 - __bfloat162float(h1)) << 16) | bfu(v0 - __bfloat162float(h0));
        if (idx < NB) g_lb[idx] = 0ull;
        return;
    }
    // histogram: 8 edges per thread (fire-and-forget RED)
    int base = (blockIdx.x - 32) * 2048 + tid * 8;
    if (base + 7 < NE) {
        int4 a = *(const int4*)(er + base);
        int4 c = *(const int4*)(er + base + 4);
        atomicAdd(&g_deg[a.x], 1);
        atomicAdd(&g_deg[a.y], 1);
        atomicAdd(&g_deg[a.z], 1);
        atomicAdd(&g_deg[a.w], 1);
        atomicAdd(&g_deg[c.x], 1);
        atomicAdd(&g_deg[c.y], 1);
        atomicAdd(&g_deg[c.z], 1);
        atomicAdd(&g_deg[c.w], 1);
    } else {
        for (int e = base; e < NE; e++) atomicAdd(&g_deg[er[e]], 1);
    }
}

// ---------------- HMMA helpers + shared GEMM tile body ----------------
__device__ __forceinline__ void mma_bf16(float* c, const uint32_t* a, uint32_t b0, uint32_t b1) {
    asm volatile(
        "mma.sync.aligned.m16n8k16.row.col.f32.bf16.bf16.f32 "
        "{%0,%1,%2,%3}, {%4,%5,%6,%7}, {%8,%9}, {%0,%1,%2,%3};"
        : "+f"(c[0]), "+f"(c[1]), "+f"(c[2]), "+f"(c[3])
        : "r"(a[0]), "r"(a[1]), "r"(a[2]), "r"(a[3]), "r"(b0), "r"(b1));
}
__device__ __forceinline__ void ldm_x4(uint32_t* a, uint32_t addr) {
    asm volatile("ldmatrix.sync.aligned.m8n8.x4.shared.b16 {%0,%1,%2,%3}, [%4];"
                 : "=r"(a[0]), "=r"(a[1]), "=r"(a[2]), "=r"(a[3]) : "r"(addr));
}

#define GSMEM (2 * 128 * ROWPAD * 2)   // A_hi + A_lo, 69632 B

__device__ __forceinline__ void gemm_tile(char* smem, int tile,
                                          const float* __restrict__ X,
                                          const float* __restrict__ Bias) {
    __nv_bfloat16* Ah = (__nv_bfloat16*)smem;
    __nv_bfloat16* Al = (__nv_bfloat16*)(smem + 128 * ROWPAD * 2);

    const int tid = threadIdx.x;
    const int w = tid >> 5;
    const int lane = tid & 31;
    const int r0 = tile * 128;

#pragma unroll
    for (int it = 0; it < 16; it++) {
        int idx = tid + it * 256;          // 4096 float4
        int row = idx >> 5;
        int kq  = idx & 31;
        float4 v = make_float4(0.f, 0.f, 0.f, 0.f);
        if (r0 + row < NN) v = *(const float4*)(X + (size_t)(r0 + row) * DD + kq * 4);
        __nv_bfloat16 hx = __float2bfloat16(v.x), hy = __float2bfloat16(v.y);
        __nv_bfloat16 hz = __float2bfloat16(v.z), hw = __float2bfloat16(v.w);
        uint32_t hi01 = ((uint32_t)__bfloat16_as_ushort(hy) << 16) | __bfloat16_as_ushort(hx);
        uint32_t hi23 = ((uint32_t)__bfloat16_as_ushort(hw) << 16) | __bfloat16_as_ushort(hz);
        uint32_t lo01 = ((uint32_t)bfu(v.y - __bfloat162float(hy)) << 16) | bfu(v.x - __bfloat162float(hx));
        uint32_t lo23 = ((uint32_t)bfu(v.w - __bfloat162float(hw)) << 16) | bfu(v.z - __bfloat162float(hz));
        *(ull*)(Ah + row * ROWPAD + kq * 4) = ((ull)hi23 << 32) | hi01;
        *(ull*)(Al + row * ROWPAD + kq * 4) = ((ull)lo23 << 32) | lo01;
    }

    uint32_t bh[2][8][2], bl[2][8][2];
#pragma unroll
    for (int t = 0; t < 2; t++)
#pragma unroll
        for (int ks = 0; ks < 8; ks++)
#pragma unroll
            for (int r = 0; r < 2; r++) {
                int gi = (((2 * w + t) * 8 + ks) * 2 + r) * 32 + lane;
                bh[t][ks][r] = g_Bfrag_hi[gi];
                bl[t][ks][r] = g_Bfrag_lo[gi];
            }

    const int t2 = lane & 3;
    const int g  = lane >> 2;
    float2 bias0 = *(const float2*)(Bias + w * 16 + t2 * 2);
    float2 bias1 = *(const float2*)(Bias + w * 16 + 8 + t2 * 2);

    __syncthreads();

    const uint32_t ah_base = smem_u32(Ah);
    const uint32_t al_base = smem_u32(Al);
    const uint32_t rowoff =
        ((((lane >> 3) & 1) * 8 + (lane & 7)) * ROWPAD + (lane >> 4) * 8) * 2;

#pragma unroll
    for (int mt = 0; mt < 8; mt++) {
        float acc0[4] = {0.f, 0.f, 0.f, 0.f};
        float acc1[4] = {0.f, 0.f, 0.f, 0.f};
#pragma unroll
        for (int ks = 0; ks < 8; ks++) {
            uint32_t off = (uint32_t)(mt * 16 * ROWPAD * 2 + ks * 32) + rowoff;
            uint32_t ah[4], al[4];
            ldm_x4(ah, ah_base + off);
            ldm_x4(al, al_base + off);
            mma_bf16(acc0, ah, bh[0][ks][0], bh[0][ks][1]);
            mma_bf16(acc1, ah, bh[1][ks][0], bh[1][ks][1]);
            mma_bf16(acc0, ah, bl[0][ks][0], bl[0][ks][1]);
            mma_bf16(acc1, ah, bl[1][ks][0], bl[1][ks][1]);
            mma_bf16(acc0, al, bh[0][ks][0], bh[0][ks][1]);
            mma_bf16(acc1, al, bh[1][ks][0], bh[1][ks][1]);
        }
        int row = r0 + mt * 16 + g;
        int col0 = w * 16 + t2 * 2;
        if (row < NN) {
            __half* q = g_hf + (size_t)row * DD;
            *(__half2*)(q + col0) =
                __float22half2_rn(make_float2(acc0[0] + bias0.x, acc0[1] + bias0.y));
            *(__half2*)(q + col0 + 8) =
                __float22half2_rn(make_float2(acc1[0] + bias1.x, acc1[1] + bias1.y));
        }
        if (row + 8 < NN) {
            __half* q = g_hf + (size_t)(row + 8) * DD;
            *(__half2*)(q + col0) =
                __float22half2_rn(make_float2(acc0[2] + bias0.x, acc0[3] + bias0.y));
            *(__half2*)(q + col0 + 8) =
                __float22half2_rn(make_float2(acc1[2] + bias1.x, acc1[3] + bias1.y));
        }
    }
}

// ---------------- launch 2: scan (blocks 0..NB-1, first wave) + gemmA (rest) ----------------
__global__ void __launch_bounds__(256) scan_gemmA_kernel(const float* __restrict__ X,
                                                         const float* __restrict__ Bias) {
    extern __shared__ char smem[];
    const int tid = threadIdx.x;

    if (blockIdx.x >= NB) {
        gemm_tile(smem, blockIdx.x - NB, X, Bias);   // tiles 0..NTA-1
        return;
    }

    // ---- decoupled-lookback scan (all NB blocks in wave 1) ----
    __shared__ int sh[256];
    __shared__ int s_prefix;
    const int bid = blockIdx.x;
    const int base = bid * 1024 + tid * 4;

    int vals[4];
    int s = 0;
#pragma unroll
    for (int k = 0; k < 4; k++) {
        int i = base + k;
        vals[k] = (i < NN) ? g_deg[i] : 0;
        if (i < NN) g_deg[i] = 0;          // restore invariant for next replay
        s += vals[k];
    }
    sh[tid] = s;
    __syncthreads();
    for (int off = 1; off < 256; off <<= 1) {
        int t = (tid >= off) ? sh[tid - off] : 0;
        __syncthreads();
        sh[tid] += t;
        __syncthreads();
    }
    const int T = sh[255];
    const int excl_local = sh[tid] - s;

    if (tid == 0) {
        ull pub = ((bid == 0) ? (2ull << 32) : (1ull << 32)) | (unsigned)T;
        atomicExch(&g_lb[bid], pub);
        if (bid == 0) s_prefix = 0;
    }
    if (bid > 0 && tid < 32) {
        int sum = 0;
        int wb = bid;
        while (true) {
            int idx = wb - 32 + tid;
            ull v;
            unsigned st;
            while (true) {
                v = (idx >= 0) ? atomicOr(&g_lb[idx], 0ull) : (2ull << 32);
                st = (unsigned)(v >> 32);
                if (__all_sync(0xffffffffu, st != 0)) break;
            }
            unsigned pmask = __ballot_sync(0xffffffffu, st == 2);
            if (pmask) {
                int lead = 31 - __clz(pmask);
                int c = (tid >= lead) ? (int)(v & 0xffffffffu) : 0;
#pragma unroll
                for (int o = 16; o; o >>= 1) c += __shfl_down_sync(0xffffffffu, c, o);
                if (tid == 0) sum += c;
                break;
            } else {
                int c = (int)(v & 0xffffffffu);
#pragma unroll
                for (int o = 16; o; o >>= 1) c += __shfl_down_sync(0xffffffffu, c, o);
                if (tid == 0) sum += c;
                wb -= 32;
            }
        }
        if (tid == 0) {
            s_prefix = sum;
            atomicExch(&g_lb[bid], (2ull << 32) | (unsigned)(sum + T));
        }
    }
    __syncthreads();

    int excl = excl_local + s_prefix;
#pragma unroll
    for (int k = 0; k < 4; k++) {
        int i = base + k;
        if (i < NN) { g_off[i] = excl; g_cur[i] = excl; }
        excl += vals[k];
    }
    if (bid == NB - 1 && tid == 255) g_off[NN] = excl;
}

// ---------------- launch 3: permute (blocks 0..NPERM-1) + gemmB (rest) ----------------
__global__ void __launch_bounds__(256) perm_gemmB_kernel(const float* __restrict__ X,
                                                         const float* __restrict__ Bias,
                                                         const int* __restrict__ er,
                                                         const int* __restrict__ ec) {
    extern __shared__ char smem[];
    const int tid = threadIdx.x;

    if (blockIdx.x >= NPERM) {
        gemm_tile(smem, NTA + (blockIdx.x - NPERM), X, Bias);   // tiles NTA..NTILE-1
        return;
    }

    // ---- permute: 8 edges per thread ----
    int base = blockIdx.x * 2048 + tid * 8;
    if (base + 7 < NE) {
        int4 r0 = *(const int4*)(er + base);
        int4 r1 = *(const int4*)(er + base + 4);
        int4 c0 = *(const int4*)(ec + base);
        int4 c1 = *(const int4*)(ec + base + 4);
        int p0 = atomicAdd(&g_cur[r0.x], 1);
        int p1 = atomicAdd(&g_cur[r0.y], 1);
        int p2 = atomicAdd(&g_cur[r0.z], 1);
        int p3 = atomicAdd(&g_cur[r0.w], 1);
        int p4 = atomicAdd(&g_cur[r1.x], 1);
        int p5 = atomicAdd(&g_cur[r1.y], 1);
        int p6 = atomicAdd(&g_cur[r1.z], 1);
        int p7 = atomicAdd(&g_cur[r1.w], 1);
        g_col[p0] = c0.x; g_col[p1] = c0.y; g_col[p2] = c0.z; g_col[p3] = c0.w;
        g_col[p4] = c1.x; g_col[p5] = c1.y; g_col[p6] = c1.z; g_col[p7] = c1.w;
    } else {
        for (int e = base; e < NE; e++) {
            int pos = atomicAdd(&g_cur[er[e]], 1);
            g_col[pos] = ec[e];
        }
    }
}

// ---------------- launch 4: gather with fp16 quad-tree accumulation ----------------
__global__ void __launch_bounds__(256) gather_kernel(float* __restrict__ out) {
    int warp = (blockIdx.x * 256 + threadIdx.x) >> 5;
    int lane = threadIdx.x & 31;
    if (warp >= NN) return;
    int beg = g_off[warp];
    int end = g_off[warp + 1];

    // self-loop, exact fp32
    uint2 sv = *(const uint2*)(g_hf + (size_t)warp * DD + lane * 4);
    float2 sf0 = __half22float2(*(__half2*)&sv.x);
    float2 sf1 = __half22float2(*(__half2*)&sv.y);
    float4 acc = make_float4(sf0.x, sf0.y, sf1.x, sf1.y);

    int e = beg;
    for (; e + 4 <= end; e += 4) {
        int c0 = g_col[e + 0];
        int c1 = g_col[e + 1];
        int c2 = g_col[e + 2];
        int c3 = g_col[e + 3];
        uint2 v0 = *(const uint2*)(g_hf + (size_t)c0 * DD + lane * 4);
        uint2 v1 = *(const uint2*)(g_hf + (size_t)c1 * DD + lane * 4);
        uint2 v2 = *(const uint2*)(g_hf + (size_t)c2 * DD + lane * 4);
        uint2 v3 = *(const uint2*)(g_hf + (size_t)c3 * DD + lane * 4);
        // fp16 quad tree: 6 HADD2, one fp32 flush
        __half2 s0 = __hadd2(*(__half2*)&v0.x, *(__half2*)&v1.x);
        __half2 s1 = __hadd2(*(__half2*)&v0.y, *(__half2*)&v1.y);
        __half2 t0 = __hadd2(*(__half2*)&v2.x, *(__half2*)&v3.x);
        __half2 t1 = __hadd2(*(__half2*)&v2.y, *(__half2*)&v3.y);
        __half2 u0 = __hadd2(s0, t0);
        __half2 u1 = __hadd2(s1, t1);
        float2 f0 = __half22float2(u0);
        float2 f1 = __half22float2(u1);
        acc.x += f0.x; acc.y += f0.y; acc.z += f1.x; acc.w += f1.y;
    }
    for (; e < end; e++) {
        uint2 v = *(const uint2*)(g_hf + (size_t)g_col[e] * DD + lane * 4);
        float2 f0 = __half22float2(*(__half2*)&v.x);
        float2 f1 = __half22float2(*(__half2*)&v.y);
        acc.x += f0.x; acc.y += f0.y; acc.z += f1.x; acc.w += f1.y;
    }

    float inv = 1.0f / (float)(end - beg + 1);
    acc.x = fmaxf(acc.x * inv, 0.f);
    acc.y = fmaxf(acc.y * inv, 0.f);
    acc.z = fmaxf(acc.z * inv, 0.f);
    acc.w = fmaxf(acc.w * inv, 0.f);
    *(float4*)(out + (size_t)warp * DD + lane * 4) = acc;
}

extern "C" void kernel_launch(void* const* d_in, const int* in_sizes, int n_in,
                              void* d_out, int out_size) {
    const float* x  = (const float*)d_in[0];
    const float* W  = (const float*)d_in[1];
    const float* b  = (const float*)d_in[2];
    const int* er   = (const int*)d_in[3];
    const int* ec   = (const int*)d_in[4];
    float* out      = (float*)d_out;

    hist_prep_kernel<<<NHIST + 32, 256>>>(er, W);

    cudaFuncSetAttribute(scan_gemmA_kernel, cudaFuncAttributeMaxDynamicSharedMemorySize, GSMEM);
    scan_gemmA_kernel<<<NB + NTA, 256, GSMEM>>>(x, b);

    cudaFuncSetAttribute(perm_gemmB_kernel, cudaFuncAttributeMaxDynamicSharedMemorySize, GSMEM);
    perm_gemmB_kernel<<<NPERM + NTB, 256, GSMEM>>>(x, b, er, ec);

    gather_kernel<<<(NN * 32 + 255) / 256, 256>>>(out);
}